// round 6
// baseline (speedup 1.0000x reference)
#include <cuda_runtime.h>
#include <cstdint>
#include <math.h>

#define T_STEPS 512
#define B_ROWS  64
#define F_DIM   256
#define U_DIM   1024
#define NB      128
#define NT      512
#define KT      128
#define AS_STRIDE 132

#define AS_BYTES (2 * B_ROWS * AS_STRIDE * 4)      // 67584
#define WS_BYTES (2 * 64 * 64 * 4)                 // 32768
#define SMEM_TOTAL (AS_BYTES + WS_BYTES)           // 100352

// ---------------- persistent device state ----------------
__device__ float g_Wr[(1280 + 2048 + 2048) * 4096]; // k-paired gate-interleaved
__device__ float g_h[2][3][B_ROWS][U_DIM];
__device__ float g_c[2][3][B_ROWS][U_DIM];
__device__ float g_emit[B_ROWS * F_DIM];

__device__ unsigned g_bar_count = 0;
__device__ volatile unsigned g_bar_gen = 0;

// Wr[k>>1][ (u*4+g)*2 + (k&1) ]  (row stride 8192 floats)
__global__ void reorder_w(const float* __restrict__ W, float* __restrict__ Wr, int total) {
    int idx = blockIdx.x * blockDim.x + threadIdx.x;
    if (idx >= total) return;
    int k = idx >> 12, n = idx & 4095;
    int g = n >> 10, u = n & 1023;
    Wr[((size_t)(k >> 1) << 13) + (((u << 2) + g) << 1) + (k & 1)] = W[idx];
}

// ---------------- grid-wide barrier ----------------
__device__ __forceinline__ void grid_barrier() {
    __syncthreads();
    if (threadIdx.x == 0) {
        __threadfence();
        unsigned gen = g_bar_gen;
        if (atomicAdd(&g_bar_count, 1u) == (unsigned)(NB - 1)) {
            g_bar_count = 0;
            __threadfence();
            g_bar_gen = gen + 1u;
        } else {
            while (g_bar_gen == gen) { }
        }
    }
    __syncthreads();
    __threadfence();  // acquire: flush stale L1
}

// ---------------- helpers ----------------
__device__ __forceinline__ float sigf(float x) { return 1.0f / (1.0f + expf(-x)); }

__device__ __forceinline__ void ffma2(unsigned long long& acc,
                                      unsigned long long a, unsigned long long b) {
    asm("fma.rn.f32x2 %0, %1, %2, %0;" : "+l"(acc) : "l"(a), "l"(b));
}
__device__ __forceinline__ float sumf2(unsigned long long v) {
    float lo = __uint_as_float((unsigned)(v & 0xffffffffu));
    float hi = __uint_as_float((unsigned)(v >> 32));
    return lo + hi;
}
__device__ __forceinline__ void cpa16(uint32_t s, const void* g) {
    asm volatile("cp.async.cg.shared.global [%0], [%1], 16;\n" :: "r"(s), "l"(g));
}
__device__ __forceinline__ void cp_commit() { asm volatile("cp.async.commit_group;\n"); }
template<int N> __device__ __forceinline__ void cp_wait() {
    asm volatile("cp.async.wait_group %0;\n" :: "n"(N));
}

// ---------------- LSTM layer phase ----------------
// CTA: 64 rows x 32 interleaved cols. Thread: 1 row x 4 cols (= 4 gates of unit u).
__device__ __forceinline__ void layer_phase(
    const float* __restrict__ A0, int lda0, int Kin,
    const float* __restrict__ Hold,
    const float* __restrict__ Wr,        // k-paired layout, row stride 8192
    const float* __restrict__ bias,      // original [4096]
    const float* __restrict__ Cold,
    float* __restrict__ Cnew, float* __restrict__ Hnew,
    float* Ash, float* Wsh, uint32_t as_u32, uint32_t ws_u32,
    int cta, int tid)
{
    const int lane = tid & 31, warp = tid >> 5;
    const int ct  = lane & 7;            // unit index u = cta*8 + ct
    const int rt  = lane >> 3;           // 0..3
    const int row = warp * 4 + rt;       // 16 warps * 4 = 64 rows
    const int ntiles = (Kin + U_DIM) / KT;

    unsigned long long acc[4];
    #pragma unroll
    for (int j = 0; j < 4; j++) acc[j] = 0ull;

    // ---- prefetch tile 0 ----
    {
        const float* Asrc = A0;          // tile 0 always in input segment (Kin>=128)
        #pragma unroll
        for (int q = 0; q < 4; q++) {
            int idx = tid + q * NT, r = idx >> 5, c4 = idx & 31;
            cpa16(as_u32 + (unsigned)((r * AS_STRIDE + c4 * 4) * 4),
                  Asrc + (size_t)r * lda0 + c4 * 4);
        }
        const float* Wt = Wr + (size_t)cta * 64;
        #pragma unroll
        for (int q = 0; q < 2; q++) {
            int idx = tid + q * NT, r = idx >> 4, c4 = idx & 15;
            cpa16(ws_u32 + (unsigned)((r * 64 + c4 * 4) * 4),
                  Wt + (size_t)r * 8192 + c4 * 4);
        }
        cp_commit();
    }

    for (int j = 0; j < ntiles; j++) {
        const int bc = j & 1;
        if (j + 1 < ntiles) {
            const int kb = (j + 1) * KT;
            const int bp = (j + 1) & 1;
            const float* Asrc; int lda, koff;
            if (kb < Kin) { Asrc = A0; lda = lda0; koff = kb; }
            else          { Asrc = Hold; lda = U_DIM; koff = kb - Kin; }
            #pragma unroll
            for (int q = 0; q < 4; q++) {
                int idx = tid + q * NT, r = idx >> 5, c4 = idx & 31;
                cpa16(as_u32 + (unsigned)(((bp * B_ROWS + r) * AS_STRIDE + c4 * 4) * 4),
                      Asrc + (size_t)r * lda + koff + c4 * 4);
            }
            const float* Wt = Wr + ((size_t)(kb >> 1)) * 8192 + cta * 64;
            #pragma unroll
            for (int q = 0; q < 2; q++) {
                int idx = tid + q * NT, r = idx >> 4, c4 = idx & 15;
                cpa16(ws_u32 + (unsigned)(((bp * 64 + r) * 64 + c4 * 4) * 4),
                      Wt + (size_t)r * 8192 + c4 * 4);
            }
            cp_commit();
            cp_wait<1>();
        } else {
            cp_wait<0>();
        }
        __syncthreads();

        const float* arow = Ash + bc * B_ROWS * AS_STRIDE + row * AS_STRIDE;
        const float* wcol = Wsh + bc * 64 * 64 + ct * 8;

        // ---- register-double-buffered inner loop ----
        ulonglong2 nA  = *(const ulonglong2*)(arow);
        ulonglong2 nW0 = *(const ulonglong2*)(wcol);        // kp row 0, gates 0,1
        ulonglong2 nW1 = *(const ulonglong2*)(wcol + 4);    // kp row 0, gates 2,3
        ulonglong2 nW2 = *(const ulonglong2*)(wcol + 64);   // kp row 1
        ulonglong2 nW3 = *(const ulonglong2*)(wcol + 68);

        #pragma unroll
        for (int k4 = 0; k4 < KT; k4 += 4) {
            ulonglong2 cA = nA, cW0 = nW0, cW1 = nW1, cW2 = nW2, cW3 = nW3;
            if (k4 + 4 < KT) {
                const float* wp = wcol + ((k4 >> 1) + 2) * 64;
                nA  = *(const ulonglong2*)(arow + k4 + 4);
                nW0 = *(const ulonglong2*)(wp);
                nW1 = *(const ulonglong2*)(wp + 4);
                nW2 = *(const ulonglong2*)(wp + 64);
                nW3 = *(const ulonglong2*)(wp + 68);
            }
            ffma2(acc[0], cA.x, cW0.x); ffma2(acc[1], cA.x, cW0.y);
            ffma2(acc[2], cA.x, cW1.x); ffma2(acc[3], cA.x, cW1.y);
            ffma2(acc[0], cA.y, cW2.x); ffma2(acc[1], cA.y, cW2.y);
            ffma2(acc[2], cA.y, cW3.x); ffma2(acc[3], cA.y, cW3.y);
        }
        __syncthreads();
    }

    // ---- in-register LSTM cell update ----
    const int u = cta * 8 + ct;
    float zi = sumf2(acc[0]) + bias[u];
    float zj = sumf2(acc[1]) + bias[1024 + u];
    float zf = sumf2(acc[2]) + bias[2048 + u];
    float zo = sumf2(acc[3]) + bias[3072 + u];
    float co = Cold[row * U_DIM + u];
    float cn = co * sigf(zf + 1.0f) + sigf(zi) * tanhf(zj);
    float hn = sigf(zo) * tanhf(cn);
    Cnew[row * U_DIM + u] = cn;
    Hnew[row * U_DIM + u] = hn;
}

// ---------------- fused dense + layernorm + relu + emit ----------------
// 64 CTAs each own one batch row; 512 threads split k in halves.
__device__ __forceinline__ void dense_ln_phase(
    const float* __restrict__ H2, const float* __restrict__ Wd,
    const float* __restrict__ bd,
    const float* __restrict__ gamma, const float* __restrict__ beta,
    float* __restrict__ out, float* h2s, float* red2, float* red,
    int t, int cta, int tid)
{
    if (cta >= B_ROWS) return;
    const int row = cta;

    ((float2*)h2s)[tid] = ((const float2*)(H2 + (size_t)row * U_DIM))[tid];
    __syncthreads();

    const int col = tid & 255;
    const int kh  = tid >> 8;            // 0 or 1
    const float* h2p = h2s + kh * 512;
    const float* wd  = Wd + (size_t)(kh * 512) * F_DIM + col;
    float acc = 0.0f;
    #pragma unroll 8
    for (int k = 0; k < 512; k++)
        acc = fmaf(h2p[k], wd[(size_t)k * F_DIM], acc);
    red2[tid] = acc;
    __syncthreads();

    float v = 0.0f;
    if (tid < 256) {
        v = red2[tid] + red2[tid + 256] + bd[tid];
        red[tid] = v;
    }
    __syncthreads();
    #pragma unroll
    for (int s = 128; s > 0; s >>= 1) {
        if (tid < s) red[tid] += red[tid + s];
        __syncthreads();
    }
    float mu = red[0] * (1.0f / 256.0f);
    __syncthreads();

    float d = v - mu;
    if (tid < 256) red[tid] = d * d;
    __syncthreads();
    #pragma unroll
    for (int s = 128; s > 0; s >>= 1) {
        if (tid < s) red[tid] += red[tid + s];
        __syncthreads();
    }
    float var = red[0] * (1.0f / 256.0f);

    if (tid < 256) {
        float o = d * rsqrtf(var + 1e-12f) * gamma[tid] + beta[tid];
        o = fmaxf(o, 0.0f);
        g_emit[row * F_DIM + tid] = o;
        out[(size_t)row * T_STEPS * F_DIM + (size_t)t * F_DIM + tid] = o;
    }
}

// ---------------- persistent kernel ----------------
__global__ void __launch_bounds__(NT, 1) lstm_persistent(
    const float* __restrict__ input, const unsigned char* __restrict__ condb,
    const float* __restrict__ b0, const float* __restrict__ b1,
    const float* __restrict__ b2,
    const float* __restrict__ Wd, const float* __restrict__ bd,
    const float* __restrict__ gamma, const float* __restrict__ beta,
    float* __restrict__ out)
{
    extern __shared__ char dynsmem[];
    float* Ash  = (float*)dynsmem;
    float* Wsh  = (float*)(dynsmem + AS_BYTES);
    float* h2s  = (float*)dynsmem;                  // dense overlays A region
    float* red2 = (float*)(dynsmem + 4096);
    float* red  = (float*)(dynsmem + 4096 + 2048);
    const uint32_t as_u32 = (uint32_t)__cvta_generic_to_shared(Ash);
    const uint32_t ws_u32 = (uint32_t)__cvta_generic_to_shared(Wsh);

    const int cta = blockIdx.x, tid = threadIdx.x;

    const float* Wr0 = g_Wr;
    const float* Wr1 = g_Wr + (size_t)1280 * 4096;
    const float* Wr2 = g_Wr + (size_t)(1280 + 2048) * 4096;

    // detect dtype of conditioned_lst: bool-u8 vs int32 vs float32
    int p1 = 0, p23 = 0;
    for (int i = tid; i < T_STEPS; i += NT) {
        unsigned char bv = condb[i];
        if (bv != 0) {
            if ((i & 3) == 1) p1 = 1;
            if ((i & 3) >= 2) p23 = 1;
        }
    }
    const int is_u8  = __syncthreads_or(p1);
    const int is_f32 = __syncthreads_or(p23) && !is_u8;
    const int*   cond32 = (const int*)condb;
    const float* condf  = (const float*)condb;

    {   // zero init ping-pong state
        float* hflat = &g_h[0][0][0][0];
        float* cflat = &g_c[0][0][0][0];
        const int tot = 2 * 3 * B_ROWS * U_DIM;
        for (int i = cta * NT + tid; i < tot; i += NB * NT) {
            hflat[i] = 0.0f; cflat[i] = 0.0f;
        }
    }
    grid_barrier();

    for (int t = 0; t < T_STEPS; t++) {
        const int p = t & 1, q = p ^ 1;
        int cv;
        if (is_u8)       cv = (int)condb[t];
        else if (is_f32) cv = (condf[t] != 0.0f);
        else             cv = cond32[t];
        const bool  use_in = (t == 0) || (cv != 0);
        const float* x  = use_in ? (input + (size_t)t * F_DIM) : g_emit;
        const int   ldx = use_in ? (T_STEPS * F_DIM) : F_DIM;

        layer_phase(x, ldx, F_DIM, &g_h[q][0][0][0], Wr0, b0,
                    &g_c[q][0][0][0], &g_c[p][0][0][0], &g_h[p][0][0][0],
                    Ash, Wsh, as_u32, ws_u32, cta, tid);
        grid_barrier();

        layer_phase(&g_h[p][0][0][0], U_DIM, U_DIM, &g_h[q][1][0][0], Wr1, b1,
                    &g_c[q][1][0][0], &g_c[p][1][0][0], &g_h[p][1][0][0],
                    Ash, Wsh, as_u32, ws_u32, cta, tid);
        grid_barrier();

        layer_phase(&g_h[p][1][0][0], U_DIM, U_DIM, &g_h[q][2][0][0], Wr2, b2,
                    &g_c[q][2][0][0], &g_c[p][2][0][0], &g_h[p][2][0][0],
                    Ash, Wsh, as_u32, ws_u32, cta, tid);
        grid_barrier();

        dense_ln_phase(&g_h[p][2][0][0], Wd, bd, gamma, beta, out,
                       h2s, red2, red, t, cta, tid);
        grid_barrier();
    }
}

extern "C" void kernel_launch(void* const* d_in, const int* in_sizes, int n_in,
                              void* d_out, int out_size) {
    (void)in_sizes; (void)n_in; (void)out_size;

    float* Wr0 = nullptr;
    cudaGetSymbolAddress((void**)&Wr0, g_Wr);
    float* Wr1 = Wr0 + (size_t)1280 * 4096;
    float* Wr2 = Wr0 + (size_t)(1280 + 2048) * 4096;

    const int t0 = 1280 * 4096, t1 = 2048 * 4096;
    reorder_w<<<(t0 + 255) / 256, 256>>>((const float*)d_in[2], Wr0, t0);
    reorder_w<<<(t1 + 255) / 256, 256>>>((const float*)d_in[4], Wr1, t1);
    reorder_w<<<(t1 + 255) / 256, 256>>>((const float*)d_in[6], Wr2, t1);

    cudaFuncSetAttribute(lstm_persistent,
                         cudaFuncAttributeMaxDynamicSharedMemorySize, SMEM_TOTAL);

    lstm_persistent<<<NB, NT, SMEM_TOTAL>>>(
        (const float*)d_in[0], (const unsigned char*)d_in[1],
        (const float*)d_in[3], (const float*)d_in[5], (const float*)d_in[7],
        (const float*)d_in[8], (const float*)d_in[9],
        (const float*)d_in[10], (const float*)d_in[11],
        (float*)d_out);
}

// round 10
// speedup vs baseline: 2.7000x; 2.7000x over previous
#include <cuda_runtime.h>
#include <cuda_bf16.h>
#include <cstdint>
#include <math.h>

#define T_STEPS 512
#define B_ROWS  64
#define F_DIM   256
#define U_DIM   1024
#define NB      128
#define NT      256
#define ROWB    144                 // smem row stride in bytes (72 bf16)

#define WB1_BASE 10485760ull        // 128*20*4096
#define WB2_BASE 27262976ull        // + 128*32*4096

// dynamic smem offsets (bytes)
#define OFF_AH0 0
#define OFF_AL0 9216
#define OFF_AH1 18432
#define OFF_AL1 27648
#define OFF_BH0 36864
#define OFF_BL0 41472
#define OFF_BH1 46080
#define OFF_BL1 50688
#define OFF_ZS  55296               // 64x36 floats = 9216B
#define DSMEM   65536

// ---------------- persistent device state ----------------
__device__ __align__(16) unsigned short g_WbT[44040192];          // [cta][chunk][hi/lo][n=32][k=64]
__device__ __align__(16) unsigned short g_x[2][B_ROWS][F_DIM];    // hi/lo input-or-emit
__device__ __align__(16) unsigned short g_hb[2][3][2][B_ROWS][U_DIM]; // [par][layer][hi/lo]
__device__ float g_c[3][B_ROWS][U_DIM];
__device__ float g_h2[B_ROWS * U_DIM];
__device__ float g_y[B_ROWS * F_DIM];
__device__ unsigned g_bar_count = 0;
__device__ volatile unsigned g_bar_gen = 0;

// ---------------- weight reorder: fp32 [K][4096] -> per-CTA [n][k] bf16 hi/lo tiles ----------------
__global__ void reorder_wb(const float* __restrict__ W, unsigned long long base,
                           int K, int nch) {
    int idx = blockIdx.x * blockDim.x + threadIdx.x;
    int total = (K >> 3) * 4096;
    if (idx >= total) return;
    int n  = idx & 4095;
    int kb = (idx >> 12) << 3;
    int g = n >> 10, u = n & 1023;
    int cta = u >> 3, nloc = ((u & 7) << 2) | g;   // gate-interleaved column
    int chunk = kb >> 6, kc = kb & 63;
    unsigned hw[4], lw[4];
    #pragma unroll
    for (int i = 0; i < 4; i++) {
        float a = W[(size_t)(kb + 2 * i) * 4096 + n];
        float b = W[(size_t)(kb + 2 * i + 1) * 4096 + n];
        __nv_bfloat16 ha = __float2bfloat16(a), hb = __float2bfloat16(b);
        float ra = a - __bfloat162float(ha), rb = b - __bfloat162float(hb);
        hw[i] = (unsigned)__bfloat16_as_ushort(ha) | ((unsigned)__bfloat16_as_ushort(hb) << 16);
        lw[i] = (unsigned)__bfloat16_as_ushort(__float2bfloat16(ra))
              | ((unsigned)__bfloat16_as_ushort(__float2bfloat16(rb)) << 16);
    }
    size_t tb = base + (size_t)(cta * nch + chunk) * 4096;
    int off = nloc * 64 + kc;
    *(uint4*)&g_WbT[tb + off]        = make_uint4(hw[0], hw[1], hw[2], hw[3]);
    *(uint4*)&g_WbT[tb + 2048 + off] = make_uint4(lw[0], lw[1], lw[2], lw[3]);
}

// ---------------- grid-wide barrier ----------------
__device__ __forceinline__ void grid_barrier() {
    __syncthreads();
    if (threadIdx.x == 0) {
        __threadfence();
        unsigned gen = g_bar_gen;
        if (atomicAdd(&g_bar_count, 1u) == (unsigned)(NB - 1)) {
            g_bar_count = 0;
            __threadfence();
            g_bar_gen = gen + 1u;
        } else {
            while (g_bar_gen == gen) { }
        }
    }
    __syncthreads();
    __threadfence();
}

// ---------------- ptx helpers ----------------
__device__ __forceinline__ float sigf(float x) { return 1.0f / (1.0f + expf(-x)); }

__device__ __forceinline__ void cpa16(uint32_t s, const void* g) {
    asm volatile("cp.async.cg.shared.global [%0], [%1], 16;\n" :: "r"(s), "l"(g));
}
__device__ __forceinline__ void cp_commit() { asm volatile("cp.async.commit_group;\n"); }
template<int N> __device__ __forceinline__ void cp_wait() {
    asm volatile("cp.async.wait_group %0;\n" :: "n"(N));
}
__device__ __forceinline__ void ldsm4(unsigned* r, uint32_t a) {
    asm volatile("ldmatrix.sync.aligned.m8n8.x4.shared.b16 {%0,%1,%2,%3}, [%4];"
                 : "=r"(r[0]), "=r"(r[1]), "=r"(r[2]), "=r"(r[3]) : "r"(a));
}
__device__ __forceinline__ void mma16816(float* d, const unsigned* a,
                                         unsigned b0, unsigned b1) {
    asm volatile(
        "mma.sync.aligned.m16n8k16.row.col.f32.bf16.bf16.f32 "
        "{%0,%1,%2,%3}, {%4,%5,%6,%7}, {%8,%9}, {%0,%1,%2,%3};"
        : "+f"(d[0]), "+f"(d[1]), "+f"(d[2]), "+f"(d[3])
        : "r"(a[0]), "r"(a[1]), "r"(a[2]), "r"(a[3]), "r"(b0), "r"(b1));
}

// ---------------- one LSTM layer: z = [feed, rec] @ W, fused gates ----------------
__device__ void layer_mma(
    const unsigned short* __restrict__ fh, const unsigned short* __restrict__ fl,
    int nf, int ldf,
    const unsigned short* __restrict__ rh, const unsigned short* __restrict__ rl,
    const unsigned short* __restrict__ wb, int nch,
    const float* __restrict__ bias, float* __restrict__ Cst,
    unsigned short* __restrict__ whi, unsigned short* __restrict__ wlo,
    float* __restrict__ h2out,
    char* db, uint32_t s0, int cta, int tid)
{
    const int lane = tid & 31, warp = tid >> 5;
    const int rg = warp & 3, cg = warp >> 2;
    const int l8 = lane & 7, gs = lane >> 3;
    const int aoff = (rg * 16 + l8 + (gs & 1) * 8) * ROWB + (gs >> 1) * 16;
    const int boff = (cg * 16 + l8 + (gs & 1) * 8) * ROWB + (gs >> 1) * 16;

    float acc[2][4] = {{0.f, 0.f, 0.f, 0.f}, {0.f, 0.f, 0.f, 0.f}};

    auto pf = [&](int j) {
        int b = j & 1;
        const unsigned short *sh, *sl; int lds, kb;
        if (j < nf) { sh = fh; sl = fl; lds = ldf; kb = j * 64; }
        else        { sh = rh; sl = rl; lds = U_DIM; kb = (j - nf) * 64; }
        uint32_t ah = s0 + (b ? OFF_AH1 : OFF_AH0);
        uint32_t al = s0 + (b ? OFF_AL1 : OFF_AL0);
        #pragma unroll
        for (int q = 0; q < 2; q++) {
            int i = tid + q * NT;
            int row = i >> 3, c8 = i & 7;
            cpa16(ah + row * ROWB + c8 * 16, sh + (size_t)row * lds + kb + c8 * 8);
            cpa16(al + row * ROWB + c8 * 16, sl + (size_t)row * lds + kb + c8 * 8);
        }
        // B tiles: 32 n-rows x 8 chunks of 16B = 256 chunks each (hi and lo)
        const unsigned short* wp = wb + (size_t)(cta * nch + j) * 4096;
        {
            int n = tid >> 3, c8 = tid & 7;
            cpa16(s0 + (b ? OFF_BH1 : OFF_BH0) + n * ROWB + c8 * 16,
                  wp + n * 64 + c8 * 8);
            cpa16(s0 + (b ? OFF_BL1 : OFF_BL0) + n * ROWB + c8 * 16,
                  wp + 2048 + n * 64 + c8 * 8);
        }
        cp_commit();
    };

    pf(0);
    for (int j = 0; j < nch; j++) {
        const int b = j & 1;
        cp_wait<0>();
        __syncthreads();                 // tiles ready; prior compute done everywhere
        if (j + 1 < nch) pf(j + 1);      // overlaps with compute below

        const uint32_t pAh = s0 + (b ? OFF_AH1 : OFF_AH0) + aoff;
        const uint32_t pAl = s0 + (b ? OFF_AL1 : OFF_AL0) + aoff;
        const uint32_t pBh = s0 + (b ? OFF_BH1 : OFF_BH0) + boff;
        const uint32_t pBl = s0 + (b ? OFF_BL1 : OFF_BL0) + boff;

        #pragma unroll
        for (int s = 0; s < 4; s++) {
            unsigned Ah[4], Al[4], Bh[4], Bl[4];
            ldsm4(Ah, pAh + s * 32);
            ldsm4(Bh, pBh + s * 32);
            ldsm4(Al, pAl + s * 32);
            ldsm4(Bl, pBl + s * 32);
            mma16816(acc[0], Ah, Bh[0], Bh[2]);
            mma16816(acc[1], Ah, Bh[1], Bh[3]);
            mma16816(acc[0], Ah, Bl[0], Bl[2]);
            mma16816(acc[1], Ah, Bl[1], Bl[3]);
            mma16816(acc[0], Al, Bh[0], Bh[2]);
            mma16816(acc[1], Al, Bh[1], Bh[3]);
        }
    }

    // ---- dump z to smem, then fused gate update ----
    float* zs = (float*)(db + OFF_ZS);
    __syncthreads();
    {
        const int r_ = rg * 16 + (lane >> 2);
        const int cb = 2 * (lane & 3);
        #pragma unroll
        for (int s = 0; s < 2; s++) {
            int col = cg * 16 + s * 8 + cb;
            *(float2*)&zs[r_ * 36 + col]       = make_float2(acc[s][0], acc[s][1]);
            *(float2*)&zs[(r_ + 8) * 36 + col] = make_float2(acc[s][2], acc[s][3]);
        }
    }
    __syncthreads();

    #pragma unroll
    for (int pp = 0; pp < 2; pp++) {
        int pidx = tid + pp * NT;
        int row = pidx >> 3, uu = pidx & 7;
        float4 zv = *(float4*)&zs[row * 36 + uu * 4];   // (i, j, f, o)
        int u = cta * 8 + uu;
        float zi = zv.x + bias[u];
        float zj = zv.y + bias[1024 + u];
        float zf = zv.z + bias[2048 + u];
        float zo = zv.w + bias[3072 + u];
        float co = Cst[row * U_DIM + u];
        float cn = co * sigf(zf + 1.0f) + sigf(zi) * tanhf(zj);
        float hn = sigf(zo) * tanhf(cn);
        Cst[row * U_DIM + u] = cn;
        __nv_bfloat16 hh = __float2bfloat16(hn);
        float rr = hn - __bfloat162float(hh);
        whi[row * U_DIM + u] = __bfloat16_as_ushort(hh);
        wlo[row * U_DIM + u] = __bfloat16_as_ushort(__float2bfloat16(rr));
        if (h2out) h2out[row * U_DIM + u] = hn;
    }
}

// ---------------- dense projection (128 CTAs: 4 row-blocks x 32 col-blocks) ----------------
__device__ void dense_phase(const float* __restrict__ Wd, const float* __restrict__ bd,
                            float* ds, int cta, int tid) {
    const int rb = cta >> 5, cb = cta & 31;
    const int r = tid >> 3, cl = tid & 7;
    const int col = cb * 8 + cl;
    float acc = 0.0f;
    for (int kb = 0; kb < U_DIM; kb += 256) {
        __syncthreads();
        #pragma unroll
        for (int qv = 0; qv < 4; qv++) {
            int idx = tid + qv * NT;
            int rr = idx >> 6, kq = idx & 63;
            *(float4*)&ds[rr * 256 + kq * 4] =
                *(const float4*)&g_h2[(size_t)(rb * 16 + rr) * U_DIM + kb + kq * 4];
        }
        __syncthreads();
        if (tid < 128) {
            #pragma unroll 8
            for (int k = 0; k < 256; k++)
                acc = fmaf(ds[r * 256 + k], Wd[(size_t)(kb + k) * F_DIM + col], acc);
        }
    }
    if (tid < 128)
        g_y[(rb * 16 + r) * F_DIM + col] = acc + bd[col];
}

// ---------------- layernorm + relu + emit + next-x hi/lo ----------------
__device__ void ln_phase(const float* __restrict__ gamma, const float* __restrict__ beta,
                         const float* __restrict__ input, float* __restrict__ out,
                         float* red, int t, int use_next, int cta, int tid) {
    if (cta >= B_ROWS) return;
    const int row = cta;
    float v = g_y[row * F_DIM + tid];

    red[tid] = v; __syncthreads();
    #pragma unroll
    for (int s = 128; s > 0; s >>= 1) {
        if (tid < s) red[tid] += red[tid + s];
        __syncthreads();
    }
    float mu = red[0] * (1.0f / 256.0f);
    __syncthreads();
    float dd = v - mu;
    red[tid] = dd * dd; __syncthreads();
    #pragma unroll
    for (int s = 128; s > 0; s >>= 1) {
        if (tid < s) red[tid] += red[tid + s];
        __syncthreads();
    }
    float var = red[0] * (1.0f / 256.0f);

    float o = dd * rsqrtf(var + 1e-12f) * gamma[tid] + beta[tid];
    o = fmaxf(o, 0.0f);
    out[((size_t)row * T_STEPS + t) * F_DIM + tid] = o;

    if (t + 1 < T_STEPS) {
        float xn = use_next ? input[((size_t)row * T_STEPS + (t + 1)) * F_DIM + tid] : o;
        __nv_bfloat16 hh = __float2bfloat16(xn);
        float rr = xn - __bfloat162float(hh);
        g_x[0][row][tid] = __bfloat16_as_ushort(hh);
        g_x[1][row][tid] = __bfloat16_as_ushort(__float2bfloat16(rr));
    }
}

// ---------------- persistent kernel ----------------
__global__ void __launch_bounds__(NT, 1) lstm_mma(
    const float* __restrict__ input, const unsigned char* __restrict__ condb,
    const float* __restrict__ b0, const float* __restrict__ b1,
    const float* __restrict__ b2,
    const float* __restrict__ Wd, const float* __restrict__ bd,
    const float* __restrict__ gamma, const float* __restrict__ beta,
    float* __restrict__ out)
{
    extern __shared__ __align__(16) char db[];
    const uint32_t s0 = (uint32_t)__cvta_generic_to_shared(db);
    float* ds  = (float*)db;                  // dense staging (A region)
    float* red = (float*)(db + OFF_ZS);       // LN reduction

    const int cta = blockIdx.x, tid = threadIdx.x;

    // detect dtype of conditioned_lst: bool-u8 vs int32 vs float32
    int p1 = 0, p23 = 0;
    for (int i = tid; i < T_STEPS; i += NT) {
        unsigned char bv = condb[i];
        if (bv != 0) { if ((i & 3) == 1) p1 = 1; if ((i & 3) >= 2) p23 = 1; }
    }
    const int is_u8  = __syncthreads_or(p1);
    const int is_f32 = __syncthreads_or(p23) && !is_u8;
    const int*   cond32 = (const int*)condb;
    const float* condf  = (const float*)condb;

    // zero c and h state; build x(0) hi/lo from input
    {
        float* cf = &g_c[0][0][0];
        for (int i = cta * NT + tid; i < 3 * B_ROWS * U_DIM; i += NB * NT) cf[i] = 0.0f;
        unsigned* hz = (unsigned*)&g_hb[0][0][0][0][0];
        for (int i = cta * NT + tid; i < 393216; i += NB * NT) hz[i] = 0u;
        for (int i = cta * NT + tid; i < B_ROWS * F_DIM; i += NB * NT) {
            int row = i >> 8, col = i & 255;
            float xv = input[(size_t)row * T_STEPS * F_DIM + col];
            __nv_bfloat16 hh = __float2bfloat16(xv);
            float rr = xv - __bfloat162float(hh);
            g_x[0][row][col] = __bfloat16_as_ushort(hh);
            g_x[1][row][col] = __bfloat16_as_ushort(__float2bfloat16(rr));
        }
    }
    grid_barrier();

    for (int t = 0; t < T_STEPS; t++) {
        const int p = t & 1, q = p ^ 1;
        int un = 0;
        if (t + 1 < T_STEPS) {
            if (is_u8)       un = (int)condb[t + 1];
            else if (is_f32) un = (condf[t + 1] != 0.0f);
            else             un = cond32[t + 1];
        }

        layer_mma(&g_x[0][0][0], &g_x[1][0][0], 4, F_DIM,
                  &g_hb[q][0][0][0][0], &g_hb[q][0][1][0][0],
                  g_WbT, 20, b0, &g_c[0][0][0],
                  &g_hb[p][0][0][0][0], &g_hb[p][0][1][0][0], nullptr,
                  db, s0, cta, tid);
        grid_barrier();

        layer_mma(&g_hb[p][0][0][0][0], &g_hb[p][0][1][0][0], 16, U_DIM,
                  &g_hb[q][1][0][0][0], &g_hb[q][1][1][0][0],
                  g_WbT + WB1_BASE, 32, b1, &g_c[1][0][0],
                  &g_hb[p][1][0][0][0], &g_hb[p][1][1][0][0], nullptr,
                  db, s0, cta, tid);
        grid_barrier();

        layer_mma(&g_hb[p][1][0][0][0], &g_hb[p][1][1][0][0], 16, U_DIM,
                  &g_hb[q][2][0][0][0], &g_hb[q][2][1][0][0],
                  g_WbT + WB2_BASE, 32, b2, &g_c[2][0][0],
                  &g_hb[p][2][0][0][0], &g_hb[p][2][1][0][0], g_h2,
                  db, s0, cta, tid);
        grid_barrier();

        dense_phase(Wd, bd, ds, cta, tid);
        grid_barrier();

        ln_phase(gamma, beta, input, out, red, t, un, cta, tid);
        grid_barrier();
    }
}

extern "C" void kernel_launch(void* const* d_in, const int* in_sizes, int n_in,
                              void* d_out, int out_size) {
    (void)in_sizes; (void)n_in; (void)out_size;

    const int tot0 = (1280 / 8) * 4096, tot1 = (2048 / 8) * 4096;
    reorder_wb<<<(tot0 + 255) / 256, 256>>>((const float*)d_in[2], 0ull, 1280, 20);
    reorder_wb<<<(tot1 + 255) / 256, 256>>>((const float*)d_in[4], WB1_BASE, 2048, 32);
    reorder_wb<<<(tot1 + 255) / 256, 256>>>((const float*)d_in[6], WB2_BASE, 2048, 32);

    cudaFuncSetAttribute(lstm_mma, cudaFuncAttributeMaxDynamicSharedMemorySize, DSMEM);

    lstm_mma<<<NB, NT, DSMEM>>>(
        (const float*)d_in[0], (const unsigned char*)d_in[1],
        (const float*)d_in[3], (const float*)d_in[5], (const float*)d_in[7],
        (const float*)d_in[8], (const float*)d_in[9],
        (const float*)d_in[10], (const float*)d_in[11],
        (float*)d_out);
}

// round 11
// speedup vs baseline: 3.9815x; 1.4746x over previous
#include <cuda_runtime.h>
#include <cuda_bf16.h>
#include <cstdint>
#include <math.h>

#define T_STEPS 512
#define B_ROWS  64
#define F_DIM   256
#define U_DIM   1024
#define NB      128
#define NT      256
#define SW(x)   ((x) ^ (((x) >> 3) & 0x70))

#define WB1_BASE 10485760ull        // 128*20*4096 (ushorts)
#define WB2_BASE 27262976ull        // + 128*32*4096

#define STG_BYTES 24576             // Ah 8K | Al 8K | Bh 4K | Bl 4K
#define NSTG      4
#define OFF_ZS    98304             // 4 stages = 98304 bytes
#define DSMEM     107520            // + zs/red 9216

// ---------------- persistent device state ----------------
__device__ __align__(16) unsigned short g_WbT[44040192];     // [cta][chunk][hi2048|lo2048] swizzled
__device__ __align__(16) unsigned short g_x[2][4][4096];     // [hi/lo][chunk] 64x64 swizzled tiles
__device__ __align__(16) unsigned short g_hb[2][3][2][16][4096]; // [par][layer][hi/lo][chunk]
__device__ float g_c[3][B_ROWS][U_DIM];
__device__ float g_h2[B_ROWS * U_DIM];
__device__ float g_y[B_ROWS * F_DIM];
__device__ unsigned g_bar_count = 0;
__device__ volatile unsigned g_bar_gen = 0;

// ---------------- weight reorder: fp32 [K][4096] -> swizzled per-CTA [n][k] hi/lo tiles ----------------
__global__ void reorder_wb(const float* __restrict__ W, unsigned long long base,
                           int K, int nch) {
    int idx = blockIdx.x * blockDim.x + threadIdx.x;
    int total = (K >> 3) * 4096;
    if (idx >= total) return;
    int n  = idx & 4095;
    int kb = (idx >> 12) << 3;
    int g = n >> 10, u = n & 1023;
    int cta = u >> 3, nloc = ((u & 7) << 2) | g;   // gate-interleaved column
    int chunk = kb >> 6, kc = kb & 63;
    unsigned hw[4], lw[4];
    #pragma unroll
    for (int i = 0; i < 4; i++) {
        float a = W[(size_t)(kb + 2 * i) * 4096 + n];
        float b = W[(size_t)(kb + 2 * i + 1) * 4096 + n];
        __nv_bfloat16 ha = __float2bfloat16(a), hb = __float2bfloat16(b);
        float ra = a - __bfloat162float(ha), rb = b - __bfloat162float(hb);
        hw[i] = (unsigned)__bfloat16_as_ushort(ha) | ((unsigned)__bfloat16_as_ushort(hb) << 16);
        lw[i] = (unsigned)__bfloat16_as_ushort(__float2bfloat16(ra))
              | ((unsigned)__bfloat16_as_ushort(__float2bfloat16(rb)) << 16);
    }
    size_t tb = base + (size_t)(cta * nch + chunk) * 4096;
    int off = SW(nloc * 128 + kc * 2) >> 1;
    *(uint4*)&g_WbT[tb + off]        = make_uint4(hw[0], hw[1], hw[2], hw[3]);
    *(uint4*)&g_WbT[tb + 2048 + off] = make_uint4(lw[0], lw[1], lw[2], lw[3]);
}

// ---------------- grid-wide barrier ----------------
__device__ __forceinline__ void grid_barrier() {
    __syncthreads();
    if (threadIdx.x == 0) {
        __threadfence();
        unsigned gen = g_bar_gen;
        if (atomicAdd(&g_bar_count, 1u) == (unsigned)(NB - 1)) {
            g_bar_count = 0;
            __threadfence();
            g_bar_gen = gen + 1u;
        } else {
            while (g_bar_gen == gen) { }
        }
    }
    __syncthreads();
    __threadfence();
}

// ---------------- ptx helpers ----------------
__device__ __forceinline__ float sigf(float x) { return 1.0f / (1.0f + expf(-x)); }

__device__ __forceinline__ void bulkcp(uint32_t dst, const void* src, uint32_t bytes,
                                       uint32_t mbar) {
    asm volatile(
        "cp.async.bulk.shared::cluster.global.mbarrier::complete_tx::bytes "
        "[%0], [%1], %2, [%3];"
        :: "r"(dst), "l"(src), "r"(bytes), "r"(mbar) : "memory");
}
__device__ __forceinline__ void mbar_init(uint32_t a, uint32_t c) {
    asm volatile("mbarrier.init.shared.b64 [%0], %1;" :: "r"(a), "r"(c) : "memory");
}
__device__ __forceinline__ void mbar_expect(uint32_t a, uint32_t bytes) {
    asm volatile("mbarrier.arrive.expect_tx.shared.b64 _, [%0], %1;"
                 :: "r"(a), "r"(bytes) : "memory");
}
__device__ __forceinline__ void mbar_wait(uint32_t a, int ph) {
    asm volatile(
        "{\n\t.reg .pred P;\n\t"
        "WL_%=:\n\t"
        "mbarrier.try_wait.parity.acquire.cta.shared::cta.b64 P, [%0], %1, 0x989680;\n\t"
        "@P bra.uni WD_%=;\n\tbra.uni WL_%=;\n\tWD_%=:\n\t}"
        :: "r"(a), "r"(ph) : "memory");
}
__device__ __forceinline__ void ldsm4(unsigned* r, uint32_t a) {
    asm volatile("ldmatrix.sync.aligned.m8n8.x4.shared.b16 {%0,%1,%2,%3}, [%4];"
                 : "=r"(r[0]), "=r"(r[1]), "=r"(r[2]), "=r"(r[3]) : "r"(a));
}
__device__ __forceinline__ void mma16816(float* d, const unsigned* a,
                                         unsigned b0, unsigned b1) {
    asm volatile(
        "mma.sync.aligned.m16n8k16.row.col.f32.bf16.bf16.f32 "
        "{%0,%1,%2,%3}, {%4,%5,%6,%7}, {%8,%9}, {%0,%1,%2,%3};"
        : "+f"(d[0]), "+f"(d[1]), "+f"(d[2]), "+f"(d[3])
        : "r"(a[0]), "r"(a[1]), "r"(a[2]), "r"(a[3]), "r"(b0), "r"(b1));
}

// ---------------- one LSTM layer: z = [feed, rec] @ W, fused gates ----------------
__device__ void layer_mma(
    const unsigned short* __restrict__ fh, const unsigned short* __restrict__ fl,
    int nf,
    const unsigned short* __restrict__ rh, const unsigned short* __restrict__ rl,
    const unsigned short* __restrict__ wb, int nch,
    const float* __restrict__ bias, float* __restrict__ Cst,
    unsigned short* __restrict__ whi, unsigned short* __restrict__ wlo,
    float* __restrict__ h2out,
    char* db, uint32_t s0, uint32_t mbb, int* ph, int cta, int tid)
{
    const int lane = tid & 31, warp = tid >> 5;
    const int rg = warp & 3, cg = warp >> 2;
    const int l8 = lane & 7, gs = lane >> 3;
    const int arow = rg * 16 + l8 + (gs & 1) * 8;        // 0..63
    const int brow = cg * 16 + l8 + (gs & 1) * 8;        // 0..31
    const int cbase = (gs >> 1) * 16;

    float acc[2][4] = {{0.f, 0.f, 0.f, 0.f}, {0.f, 0.f, 0.f, 0.f}};

    auto issue = [&](int j) {
        if (tid == 0) {
            int s = j & (NSTG - 1);
            uint32_t mb = mbb + s * 8;
            mbar_expect(mb, STG_BYTES);
            const unsigned short *ah, *al;
            if (j < nf) { ah = fh + (size_t)j * 4096; al = fl + (size_t)j * 4096; }
            else { ah = rh + (size_t)(j - nf) * 4096; al = rl + (size_t)(j - nf) * 4096; }
            const unsigned short* wp = wb + (size_t)(cta * nch + j) * 4096;
            uint32_t d = s0 + s * STG_BYTES;
            bulkcp(d,         ah, 8192, mb);
            bulkcp(d + 8192,  al, 8192, mb);
            bulkcp(d + 16384, wp, 4096, mb);
            bulkcp(d + 20480, wp + 2048, 4096, mb);
        }
    };

    #pragma unroll
    for (int j0 = 0; j0 < NSTG; j0++) if (j0 < nch) issue(j0);

    for (int j = 0; j < nch; j++) {
        const int s = j & (NSTG - 1);
        mbar_wait(mbb + s * 8, ph[s]);
        ph[s] ^= 1;

        const uint32_t bA  = s0 + s * STG_BYTES;
        const uint32_t bAl = bA + 8192;
        const uint32_t bB  = bA + 16384;
        const uint32_t bBl = bA + 20480;

        #pragma unroll
        for (int s4 = 0; s4 < 4; s4++) {
            unsigned Ah[4], Al[4], Bh[4], Bl[4];
            const uint32_t ao = SW(arow * 128 + cbase + s4 * 32);
            const uint32_t bo = SW(brow * 128 + cbase + s4 * 32);
            ldsm4(Ah, bA  + ao);
            ldsm4(Bh, bB  + bo);
            ldsm4(Al, bAl + ao);
            ldsm4(Bl, bBl + bo);
            mma16816(acc[0], Ah, Bh[0], Bh[2]);
            mma16816(acc[1], Ah, Bh[1], Bh[3]);
            mma16816(acc[0], Ah, Bl[0], Bl[2]);
            mma16816(acc[1], Ah, Bl[1], Bl[3]);
            mma16816(acc[0], Al, Bh[0], Bh[2]);
            mma16816(acc[1], Al, Bh[1], Bh[3]);
        }
        __syncthreads();               // all warps done reading stage s
        if (j + NSTG < nch) issue(j + NSTG);
    }

    // ---- dump z to smem, then fused gate update ----
    float* zs = (float*)(db + OFF_ZS);
    __syncthreads();
    {
        const int r_ = rg * 16 + (lane >> 2);
        const int cb = 2 * (lane & 3);
        #pragma unroll
        for (int s = 0; s < 2; s++) {
            int col = cg * 16 + s * 8 + cb;
            *(float2*)&zs[r_ * 36 + col]       = make_float2(acc[s][0], acc[s][1]);
            *(float2*)&zs[(r_ + 8) * 36 + col] = make_float2(acc[s][2], acc[s][3]);
        }
    }
    __syncthreads();

    #pragma unroll
    for (int pp = 0; pp < 2; pp++) {
        int pidx = tid + pp * NT;
        int row = pidx >> 3, uu = pidx & 7;
        float4 zv = *(float4*)&zs[row * 36 + uu * 4];   // (i, j, f, o)
        int u = cta * 8 + uu;
        float zi = zv.x + bias[u];
        float zj = zv.y + bias[1024 + u];
        float zf = zv.z + bias[2048 + u];
        float zo = zv.w + bias[3072 + u];
        float co = Cst[row * U_DIM + u];
        float cn = co * sigf(zf + 1.0f) + sigf(zi) * tanhf(zj);
        float hn = sigf(zo) * tanhf(cn);
        Cst[row * U_DIM + u] = cn;
        __nv_bfloat16 hh = __float2bfloat16(hn);
        float rr = hn - __bfloat162float(hh);
        int uc = u >> 6;
        int off = SW(row * 128 + (u & 63) * 2) >> 1;
        whi[uc * 4096 + off] = __bfloat16_as_ushort(hh);
        wlo[uc * 4096 + off] = __bfloat16_as_ushort(__float2bfloat16(rr));
        if (h2out) h2out[row * U_DIM + u] = hn;
    }
}

// ---------------- dense projection (128 CTAs: 4 row-blocks x 32 col-blocks) ----------------
__device__ void dense_phase(const float* __restrict__ Wd, const float* __restrict__ bd,
                            float* ds, int cta, int tid) {
    const int rb = cta >> 5, cb = cta & 31;
    const int r = tid >> 3, cl = tid & 7;
    const int col = cb * 8 + cl;
    float acc = 0.0f;
    for (int kb = 0; kb < U_DIM; kb += 256) {
        __syncthreads();
        #pragma unroll
        for (int qv = 0; qv < 4; qv++) {
            int idx = tid + qv * NT;
            int rr = idx >> 6, kq = idx & 63;
            *(float4*)&ds[rr * 256 + kq * 4] =
                *(const float4*)&g_h2[(size_t)(rb * 16 + rr) * U_DIM + kb + kq * 4];
        }
        __syncthreads();
        if (tid < 128) {
            #pragma unroll 8
            for (int k = 0; k < 256; k++)
                acc = fmaf(ds[r * 256 + k], Wd[(size_t)(kb + k) * F_DIM + col], acc);
        }
    }
    if (tid < 128)
        g_y[(rb * 16 + r) * F_DIM + col] = acc + bd[col];
}

// ---------------- layernorm + relu + emit + next-x tiles ----------------
__device__ void ln_phase(const float* __restrict__ gamma, const float* __restrict__ beta,
                         const float* __restrict__ input, float* __restrict__ out,
                         float* red, int t, int use_next, int cta, int tid) {
    if (cta >= B_ROWS) return;
    const int row = cta;
    float v = g_y[row * F_DIM + tid];

    red[tid] = v; __syncthreads();
    #pragma unroll
    for (int s = 128; s > 0; s >>= 1) {
        if (tid < s) red[tid] += red[tid + s];
        __syncthreads();
    }
    float mu = red[0] * (1.0f / 256.0f);
    __syncthreads();
    float dd = v - mu;
    red[tid] = dd * dd; __syncthreads();
    #pragma unroll
    for (int s = 128; s > 0; s >>= 1) {
        if (tid < s) red[tid] += red[tid + s];
        __syncthreads();
    }
    float var = red[0] * (1.0f / 256.0f);

    float o = dd * rsqrtf(var + 1e-12f) * gamma[tid] + beta[tid];
    o = fmaxf(o, 0.0f);
    out[((size_t)row * T_STEPS + t) * F_DIM + tid] = o;

    if (t + 1 < T_STEPS) {
        float xn = use_next ? input[((size_t)row * T_STEPS + (t + 1)) * F_DIM + tid] : o;
        __nv_bfloat16 hh = __float2bfloat16(xn);
        float rr = xn - __bfloat162float(hh);
        int chunk = tid >> 6;
        int off = SW(row * 128 + (tid & 63) * 2) >> 1;
        g_x[0][chunk][off] = __bfloat16_as_ushort(hh);
        g_x[1][chunk][off] = __bfloat16_as_ushort(__float2bfloat16(rr));
    }
}

// ---------------- persistent kernel ----------------
__global__ void __launch_bounds__(NT, 1) lstm_mma(
    const float* __restrict__ input, const unsigned char* __restrict__ condb,
    const float* __restrict__ b0, const float* __restrict__ b1,
    const float* __restrict__ b2,
    const float* __restrict__ Wd, const float* __restrict__ bd,
    const float* __restrict__ gamma, const float* __restrict__ beta,
    float* __restrict__ out)
{
    extern __shared__ __align__(128) char db[];
    const uint32_t s0 = (uint32_t)__cvta_generic_to_shared(db);
    float* ds  = (float*)db;                  // dense staging (stage region)
    float* red = (float*)(db + OFF_ZS);       // LN reduction

    __shared__ __align__(8) unsigned long long s_mb[NSTG];
    const uint32_t mbb = (uint32_t)__cvta_generic_to_shared(&s_mb[0]);

    const int cta = blockIdx.x, tid = threadIdx.x;
    int ph[NSTG] = {0, 0, 0, 0};

    if (tid == 0)
        for (int s = 0; s < NSTG; s++) mbar_init(mbb + s * 8, 1);
    __syncthreads();

    // detect dtype of conditioned_lst: bool-u8 vs int32 vs float32
    int p1 = 0, p23 = 0;
    for (int i = tid; i < T_STEPS; i += NT) {
        unsigned char bv = condb[i];
        if (bv != 0) { if ((i & 3) == 1) p1 = 1; if ((i & 3) >= 2) p23 = 1; }
    }
    const int is_u8  = __syncthreads_or(p1);
    const int is_f32 = __syncthreads_or(p23) && !is_u8;
    const int*   cond32 = (const int*)condb;
    const float* condf  = (const float*)condb;

    // zero c and h state; build x(0) tiles from input
    {
        float* cf = &g_c[0][0][0];
        for (int i = cta * NT + tid; i < 3 * B_ROWS * U_DIM; i += NB * NT) cf[i] = 0.0f;
        unsigned* hz = (unsigned*)&g_hb[0][0][0][0][0];
        for (int i = cta * NT + tid; i < 393216; i += NB * NT) hz[i] = 0u;
        for (int i = cta * NT + tid; i < B_ROWS * F_DIM; i += NB * NT) {
            int row = i >> 8, col = i & 255;
            float xv = input[(size_t)row * T_STEPS * F_DIM + col];
            __nv_bfloat16 hh = __float2bfloat16(xv);
            float rr = xv - __bfloat162float(hh);
            int chunk = col >> 6;
            int off = SW(row * 128 + (col & 63) * 2) >> 1;
            g_x[0][chunk][off] = __bfloat16_as_ushort(hh);
            g_x[1][chunk][off] = __bfloat16_as_ushort(__float2bfloat16(rr));
        }
    }
    grid_barrier();

    for (int t = 0; t < T_STEPS; t++) {
        const int p = t & 1, q = p ^ 1;
        int un = 0;
        if (t + 1 < T_STEPS) {
            if (is_u8)       un = (int)condb[t + 1];
            else if (is_f32) un = (condf[t + 1] != 0.0f);
            else             un = cond32[t + 1];
        }

        layer_mma(&g_x[0][0][0], &g_x[1][0][0], 4,
                  &g_hb[q][0][0][0][0], &g_hb[q][0][1][0][0],
                  g_WbT, 20, b0, &g_c[0][0][0],
                  &g_hb[p][0][0][0][0], &g_hb[p][0][1][0][0], nullptr,
                  db, s0, mbb, ph, cta, tid);
        grid_barrier();

        layer_mma(&g_hb[p][0][0][0][0], &g_hb[p][0][1][0][0], 16,
                  &g_hb[q][1][0][0][0], &g_hb[q][1][1][0][0],
                  g_WbT + WB1_BASE, 32, b1, &g_c[1][0][0],
                  &g_hb[p][1][0][0][0], &g_hb[p][1][1][0][0], nullptr,
                  db, s0, mbb, ph, cta, tid);
        grid_barrier();

        layer_mma(&g_hb[p][1][0][0][0], &g_hb[p][1][1][0][0], 16,
                  &g_hb[q][2][0][0][0], &g_hb[q][2][1][0][0],
                  g_WbT + WB2_BASE, 32, b2, &g_c[2][0][0],
                  &g_hb[p][2][0][0][0], &g_hb[p][2][1][0][0], g_h2,
                  db, s0, mbb, ph, cta, tid);
        grid_barrier();

        dense_phase(Wd, bd, ds, cta, tid);
        grid_barrier();

        ln_phase(gamma, beta, input, out, red, t, un, cta, tid);
        grid_barrier();
    }
}

extern "C" void kernel_launch(void* const* d_in, const int* in_sizes, int n_in,
                              void* d_out, int out_size) {
    (void)in_sizes; (void)n_in; (void)out_size;

    const int tot0 = (1280 / 8) * 4096, tot1 = (2048 / 8) * 4096;
    reorder_wb<<<(tot0 + 255) / 256, 256>>>((const float*)d_in[2], 0ull, 1280, 20);
    reorder_wb<<<(tot1 + 255) / 256, 256>>>((const float*)d_in[4], WB1_BASE, 2048, 32);
    reorder_wb<<<(tot1 + 255) / 256, 256>>>((const float*)d_in[6], WB2_BASE, 2048, 32);

    cudaFuncSetAttribute(lstm_mma, cudaFuncAttributeMaxDynamicSharedMemorySize, DSMEM);

    lstm_mma<<<NB, NT, DSMEM>>>(
        (const float*)d_in[0], (const unsigned char*)d_in[1],
        (const float*)d_in[3], (const float*)d_in[5], (const float*)d_in[7],
        (const float*)d_in[8], (const float*)d_in[9],
        (const float*)d_in[10], (const float*)d_in[11],
        (float*)d_out);
}

// round 12
// speedup vs baseline: 5.2520x; 1.3191x over previous
#include <cuda_runtime.h>
#include <cuda_bf16.h>
#include <cstdint>
#include <math.h>

#define T_STEPS 512
#define B_ROWS  64
#define F_DIM   256
#define U_DIM   1024
#define NB      128
#define NT      512
#define SW(x)   ((x) ^ (((x) >> 3) & 0x70))

#define WB1_BASE 10485760ull        // 128*20*4096 (ushorts)
#define WB2_BASE 27262976ull        // + 128*32*4096

#define STG_BYTES 24576             // Ah 8K | Al 8K | Bh 4K | Bl 4K
#define OFF_ZS    98304             // 4 stage buffers end here
#define ZS_STRIDE 9216              // per-group partial z (64x36 floats)
#define DSMEM     116736            // 98304 + 2*9216

// ---------------- persistent device state ----------------
__device__ __align__(16) unsigned short g_WbT[44040192];     // [cta][chunk][hi2048|lo2048] swizzled
__device__ __align__(16) unsigned short g_x[2][4][4096];     // [hi/lo][chunk] 64x64 swizzled tiles
__device__ __align__(16) unsigned short g_hb[2][3][2][16][4096]; // [par][layer][hi/lo][chunk]
__device__ float g_c[3][B_ROWS][U_DIM];
__device__ float g_h2[B_ROWS * U_DIM];
__device__ unsigned g_bar_count = 0;
__device__ volatile unsigned g_bar_gen = 0;

// ---------------- weight reorder: fp32 [K][4096] -> swizzled per-CTA [n][k] hi/lo tiles ----------------
__global__ void reorder_wb(const float* __restrict__ W, unsigned long long base,
                           int K, int nch) {
    int idx = blockIdx.x * blockDim.x + threadIdx.x;
    int total = (K >> 3) * 4096;
    if (idx >= total) return;
    int n  = idx & 4095;
    int kb = (idx >> 12) << 3;
    int g = n >> 10, u = n & 1023;
    int cta = u >> 3, nloc = ((u & 7) << 2) | g;   // gate-interleaved column
    int chunk = kb >> 6, kc = kb & 63;
    unsigned hw[4], lw[4];
    #pragma unroll
    for (int i = 0; i < 4; i++) {
        float a = W[(size_t)(kb + 2 * i) * 4096 + n];
        float b = W[(size_t)(kb + 2 * i + 1) * 4096 + n];
        __nv_bfloat16 ha = __float2bfloat16(a), hb = __float2bfloat16(b);
        float ra = a - __bfloat162float(ha), rb = b - __bfloat162float(hb);
        hw[i] = (unsigned)__bfloat16_as_ushort(ha) | ((unsigned)__bfloat16_as_ushort(hb) << 16);
        lw[i] = (unsigned)__bfloat16_as_ushort(__float2bfloat16(ra))
              | ((unsigned)__bfloat16_as_ushort(__float2bfloat16(rb)) << 16);
    }
    size_t tb = base + (size_t)(cta * nch + chunk) * 4096;
    int off = SW(nloc * 128 + kc * 2) >> 1;
    *(uint4*)&g_WbT[tb + off]        = make_uint4(hw[0], hw[1], hw[2], hw[3]);
    *(uint4*)&g_WbT[tb + 2048 + off] = make_uint4(lw[0], lw[1], lw[2], lw[3]);
}

// ---------------- grid-wide barrier ----------------
__device__ __forceinline__ void grid_barrier() {
    __syncthreads();
    if (threadIdx.x == 0) {
        __threadfence();
        unsigned gen = g_bar_gen;
        if (atomicAdd(&g_bar_count, 1u) == (unsigned)(NB - 1)) {
            g_bar_count = 0;
            __threadfence();
            g_bar_gen = gen + 1u;
        } else {
            while (g_bar_gen == gen) { }
        }
    }
    __syncthreads();
    __threadfence();
}

// ---------------- ptx helpers ----------------
__device__ __forceinline__ float sigf(float x) { return 1.0f / (1.0f + expf(-x)); }

__device__ __forceinline__ void bulkcp(uint32_t dst, const void* src, uint32_t bytes,
                                       uint32_t mbar) {
    asm volatile(
        "cp.async.bulk.shared::cluster.global.mbarrier::complete_tx::bytes "
        "[%0], [%1], %2, [%3];"
        :: "r"(dst), "l"(src), "r"(bytes), "r"(mbar) : "memory");
}
__device__ __forceinline__ void mbar_init(uint32_t a, uint32_t c) {
    asm volatile("mbarrier.init.shared.b64 [%0], %1;" :: "r"(a), "r"(c) : "memory");
}
__device__ __forceinline__ void mbar_expect(uint32_t a, uint32_t bytes) {
    asm volatile("mbarrier.arrive.expect_tx.shared.b64 _, [%0], %1;"
                 :: "r"(a), "r"(bytes) : "memory");
}
__device__ __forceinline__ void mbar_wait(uint32_t a, int ph) {
    asm volatile(
        "{\n\t.reg .pred P;\n\t"
        "WL_%=:\n\t"
        "mbarrier.try_wait.parity.acquire.cta.shared::cta.b64 P, [%0], %1, 0x989680;\n\t"
        "@P bra.uni WD_%=;\n\tbra.uni WL_%=;\n\tWD_%=:\n\t}"
        :: "r"(a), "r"(ph) : "memory");
}
__device__ __forceinline__ void group_bar(int g) {
    asm volatile("bar.sync %0, 256;" :: "r"(g + 1) : "memory");
}
__device__ __forceinline__ void ldsm4(unsigned* r, uint32_t a) {
    asm volatile("ldmatrix.sync.aligned.m8n8.x4.shared.b16 {%0,%1,%2,%3}, [%4];"
                 : "=r"(r[0]), "=r"(r[1]), "=r"(r[2]), "=r"(r[3]) : "r"(a));
}
__device__ __forceinline__ void mma16816(float* d, const unsigned* a,
                                         unsigned b0, unsigned b1) {
    asm volatile(
        "mma.sync.aligned.m16n8k16.row.col.f32.bf16.bf16.f32 "
        "{%0,%1,%2,%3}, {%4,%5,%6,%7}, {%8,%9}, {%0,%1,%2,%3};"
        : "+f"(d[0]), "+f"(d[1]), "+f"(d[2]), "+f"(d[3])
        : "r"(a[0]), "r"(a[1]), "r"(a[2]), "r"(a[3]), "r"(b0), "r"(b1));
}

// ---------------- one LSTM layer: z = [feed, rec] @ W, fused gates ----------------
// 2 warp groups (8 warps each) split K by chunk parity; partial z summed in epilogue.
__device__ void layer_mma(
    const unsigned short* __restrict__ fh, const unsigned short* __restrict__ fl,
    int nf,
    const unsigned short* __restrict__ rh, const unsigned short* __restrict__ rl,
    const unsigned short* __restrict__ wb, int nch,
    const float* __restrict__ bias, float* __restrict__ Cst,
    unsigned short* __restrict__ whi, unsigned short* __restrict__ wlo,
    float* __restrict__ h2out,
    char* db, uint32_t s0, uint32_t mbb, int* ph, int cta, int tid)
{
    const int g   = tid >> 8;            // warp group 0/1
    const int gt  = tid & 255;
    const int lane = tid & 31, warp = gt >> 5;
    const int rg = warp & 3, cg = warp >> 2;
    const int l8 = lane & 7, gs = lane >> 3;
    const int arow = rg * 16 + l8 + (gs & 1) * 8;        // 0..63
    const int brow = cg * 16 + l8 + (gs & 1) * 8;        // 0..31
    const int cbase = (gs >> 1) * 16;
    const int nj = nch >> 1;             // chunks per group

    // separate accumulators per precision pass (shallow HMMA chains)
    float acc[3][2][4];
    #pragma unroll
    for (int p_ = 0; p_ < 3; p_++)
        #pragma unroll
        for (int c_ = 0; c_ < 2; c_++)
            #pragma unroll
            for (int f_ = 0; f_ < 4; f_++) acc[p_][c_][f_] = 0.f;

    auto issue = [&](int jj) {
        if (gt == 0) {
            int j = jj * 2 + g;
            int buf = g * 2 + (jj & 1);
            uint32_t mb = mbb + buf * 8;
            mbar_expect(mb, STG_BYTES);
            const unsigned short *ah, *al;
            if (j < nf) { ah = fh + (size_t)j * 4096; al = fl + (size_t)j * 4096; }
            else { ah = rh + (size_t)(j - nf) * 4096; al = rl + (size_t)(j - nf) * 4096; }
            const unsigned short* wp = wb + (size_t)(cta * nch + j) * 4096;
            uint32_t d = s0 + buf * STG_BYTES;
            bulkcp(d,         ah, 8192, mb);
            bulkcp(d + 8192,  al, 8192, mb);
            bulkcp(d + 16384, wp, 4096, mb);
            bulkcp(d + 20480, wp + 2048, 4096, mb);
        }
    };

    issue(0); issue(1);
    for (int jj = 0; jj < nj; jj++) {
        const int buf = g * 2 + (jj & 1);
        mbar_wait(mbb + buf * 8, ph[buf]);
        ph[buf] ^= 1;

        const uint32_t bA  = s0 + buf * STG_BYTES;
        const uint32_t bAl = bA + 8192;
        const uint32_t bB  = bA + 16384;
        const uint32_t bBl = bA + 20480;

        #pragma unroll
        for (int s4 = 0; s4 < 4; s4++) {
            unsigned Ah[4], Al[4], Bh[4], Bl[4];
            const uint32_t ao = SW(arow * 128 + cbase + s4 * 32);
            const uint32_t bo = SW(brow * 128 + cbase + s4 * 32);
            ldsm4(Ah, bA  + ao);
            ldsm4(Bh, bB  + bo);
            ldsm4(Al, bAl + ao);
            ldsm4(Bl, bBl + bo);
            mma16816(acc[0][0], Ah, Bh[0], Bh[2]);
            mma16816(acc[0][1], Ah, Bh[1], Bh[3]);
            mma16816(acc[1][0], Ah, Bl[0], Bl[2]);
            mma16816(acc[1][1], Ah, Bl[1], Bl[3]);
            mma16816(acc[2][0], Al, Bh[0], Bh[2]);
            mma16816(acc[2][1], Al, Bh[1], Bh[3]);
        }
        group_bar(g);                  // group's warps done reading buf
        if (jj + 2 < nj) issue(jj + 2);
    }

    // ---- dump group's partial z to its zs buffer ----
    float* zs = (float*)(db + OFF_ZS + g * ZS_STRIDE);
    {
        const int r_ = rg * 16 + (lane >> 2);
        const int cb = 2 * (lane & 3);
        #pragma unroll
        for (int s = 0; s < 2; s++) {
            int col = cg * 16 + s * 8 + cb;
            float v0 = acc[0][s][0] + acc[1][s][0] + acc[2][s][0];
            float v1 = acc[0][s][1] + acc[1][s][1] + acc[2][s][1];
            float v2 = acc[0][s][2] + acc[1][s][2] + acc[2][s][2];
            float v3 = acc[0][s][3] + acc[1][s][3] + acc[2][s][3];
            *(float2*)&zs[r_ * 36 + col]       = make_float2(v0, v1);
            *(float2*)&zs[(r_ + 8) * 36 + col] = make_float2(v2, v3);
        }
    }
    __syncthreads();

    // ---- fused gate update: 512 threads, 1 cell each ----
    {
        float* zs0 = (float*)(db + OFF_ZS);
        float* zs1 = (float*)(db + OFF_ZS + ZS_STRIDE);
        int row = tid >> 3, uu = tid & 7;
        float4 za = *(float4*)&zs0[row * 36 + uu * 4];
        float4 zb = *(float4*)&zs1[row * 36 + uu * 4];
        int u = cta * 8 + uu;
        float zi = za.x + zb.x + bias[u];
        float zj = za.y + zb.y + bias[1024 + u];
        float zf = za.z + zb.z + bias[2048 + u];
        float zo = za.w + zb.w + bias[3072 + u];
        float co = Cst[row * U_DIM + u];
        float cn = co * sigf(zf + 1.0f) + sigf(zi) * tanhf(zj);
        float hn = sigf(zo) * tanhf(cn);
        Cst[row * U_DIM + u] = cn;
        __nv_bfloat16 hh = __float2bfloat16(hn);
        float rr = hn - __bfloat162float(hh);
        int uc = u >> 6;
        int off = SW(row * 128 + (u & 63) * 2) >> 1;
        whi[uc * 4096 + off] = __bfloat16_as_ushort(hh);
        wlo[uc * 4096 + off] = __bfloat16_as_ushort(__float2bfloat16(rr));
        if (h2out) h2out[row * U_DIM + u] = hn;
    }
}

// ---------------- fused dense + layernorm + relu + emit (64 row-owner CTAs) ----------------
__device__ void dense_ln_phase(
    const float* __restrict__ Wd, const float* __restrict__ bd,
    const float* __restrict__ gamma, const float* __restrict__ beta,
    const float* __restrict__ input, float* __restrict__ out,
    char* db, int t, int use_next, int cta, int tid)
{
    if (cta >= B_ROWS) return;
    const int row = cta;
    float* h2s  = (float*)db;             // 4KB
    float* red2 = (float*)(db + 4096);    // 2KB
    float* red  = (float*)(db + 6144);    // 1KB

    ((float2*)h2s)[tid] = ((const float2*)(g_h2 + (size_t)row * U_DIM))[tid];
    __syncthreads();

    const int col = tid & 255;
    const int kh  = tid >> 8;
    const float* h2p = h2s + kh * 512;
    const float* wd  = Wd + (size_t)(kh * 512) * F_DIM + col;
    float acc = 0.0f;
    #pragma unroll 8
    for (int k = 0; k < 512; k++)
        acc = fmaf(h2p[k], wd[(size_t)k * F_DIM], acc);
    red2[tid] = acc;
    __syncthreads();

    float v = 0.0f;
    if (tid < 256) {
        v = red2[tid] + red2[tid + 256] + bd[tid];
        red[tid] = v;
    }
    __syncthreads();
    #pragma unroll
    for (int s = 128; s > 0; s >>= 1) {
        if (tid < s) red[tid] += red[tid + s];
        __syncthreads();
    }
    float mu = red[0] * (1.0f / 256.0f);
    __syncthreads();
    float dd = v - mu;
    if (tid < 256) red[tid] = dd * dd;
    __syncthreads();
    #pragma unroll
    for (int s = 128; s > 0; s >>= 1) {
        if (tid < s) red[tid] += red[tid + s];
        __syncthreads();
    }
    float var = red[0] * (1.0f / 256.0f);

    if (tid < 256) {
        float o = dd * rsqrtf(var + 1e-12f) * gamma[tid] + beta[tid];
        o = fmaxf(o, 0.0f);
        out[((size_t)row * T_STEPS + t) * F_DIM + tid] = o;
        if (t + 1 < T_STEPS) {
            float xn = use_next ? input[((size_t)row * T_STEPS + (t + 1)) * F_DIM + tid] : o;
            __nv_bfloat16 hh = __float2bfloat16(xn);
            float rr = xn - __bfloat162float(hh);
            int chunk = tid >> 6;
            int off = SW(row * 128 + (tid & 63) * 2) >> 1;
            g_x[0][chunk][off] = __bfloat16_as_ushort(hh);
            g_x[1][chunk][off] = __bfloat16_as_ushort(__float2bfloat16(rr));
        }
    }
}

// ---------------- persistent kernel ----------------
__global__ void __launch_bounds__(NT, 1) lstm_mma(
    const float* __restrict__ input, const unsigned char* __restrict__ condb,
    const float* __restrict__ b0, const float* __restrict__ b1,
    const float* __restrict__ b2,
    const float* __restrict__ Wd, const float* __restrict__ bd,
    const float* __restrict__ gamma, const float* __restrict__ beta,
    float* __restrict__ out)
{
    extern __shared__ __align__(128) char db[];
    const uint32_t s0 = (uint32_t)__cvta_generic_to_shared(db);

    __shared__ __align__(8) unsigned long long s_mb[4];
    const uint32_t mbb = (uint32_t)__cvta_generic_to_shared(&s_mb[0]);

    const int cta = blockIdx.x, tid = threadIdx.x;
    int ph[4] = {0, 0, 0, 0};

    if (tid == 0)
        for (int s = 0; s < 4; s++) mbar_init(mbb + s * 8, 1);
    __syncthreads();

    // detect dtype of conditioned_lst: bool-u8 vs int32 vs float32
    int p1 = 0, p23 = 0;
    for (int i = tid; i < T_STEPS; i += NT) {
        unsigned char bv = condb[i];
        if (bv != 0) { if ((i & 3) == 1) p1 = 1; if ((i & 3) >= 2) p23 = 1; }
    }
    const int is_u8  = __syncthreads_or(p1);
    const int is_f32 = __syncthreads_or(p23) && !is_u8;
    const int*   cond32 = (const int*)condb;
    const float* condf  = (const float*)condb;

    // zero c and h state; build x(0) tiles from input
    {
        float* cf = &g_c[0][0][0];
        for (int i = cta * NT + tid; i < 3 * B_ROWS * U_DIM; i += NB * NT) cf[i] = 0.0f;
        unsigned* hz = (unsigned*)&g_hb[0][0][0][0][0];
        for (int i = cta * NT + tid; i < 393216; i += NB * NT) hz[i] = 0u;
        for (int i = cta * NT + tid; i < B_ROWS * F_DIM; i += NB * NT) {
            int row = i >> 8, col = i & 255;
            float xv = input[(size_t)row * T_STEPS * F_DIM + col];
            __nv_bfloat16 hh = __float2bfloat16(xv);
            float rr = xv - __bfloat162float(hh);
            int chunk = col >> 6;
            int off = SW(row * 128 + (col & 63) * 2) >> 1;
            g_x[0][chunk][off] = __bfloat16_as_ushort(hh);
            g_x[1][chunk][off] = __bfloat16_as_ushort(__float2bfloat16(rr));
        }
    }
    grid_barrier();

    for (int t = 0; t < T_STEPS; t++) {
        const int p = t & 1, q = p ^ 1;
        int un = 0;
        if (t + 1 < T_STEPS) {
            if (is_u8)       un = (int)condb[t + 1];
            else if (is_f32) un = (condf[t + 1] != 0.0f);
            else             un = cond32[t + 1];
        }

        layer_mma(&g_x[0][0][0], &g_x[1][0][0], 4,
                  &g_hb[q][0][0][0][0], &g_hb[q][0][1][0][0],
                  g_WbT, 20, b0, &g_c[0][0][0],
                  &g_hb[p][0][0][0][0], &g_hb[p][0][1][0][0], nullptr,
                  db, s0, mbb, ph, cta, tid);
        grid_barrier();

        layer_mma(&g_hb[p][0][0][0][0], &g_hb[p][0][1][0][0], 16,
                  &g_hb[q][1][0][0][0], &g_hb[q][1][1][0][0],
                  g_WbT + WB1_BASE, 32, b1, &g_c[1][0][0],
                  &g_hb[p][1][0][0][0], &g_hb[p][1][1][0][0], nullptr,
                  db, s0, mbb, ph, cta, tid);
        grid_barrier();

        layer_mma(&g_hb[p][1][0][0][0], &g_hb[p][1][1][0][0], 16,
                  &g_hb[q][2][0][0][0], &g_hb[q][2][1][0][0],
                  g_WbT + WB2_BASE, 32, b2, &g_c[2][0][0],
                  &g_hb[p][2][0][0][0], &g_hb[p][2][1][0][0], g_h2,
                  db, s0, mbb, ph, cta, tid);
        grid_barrier();

        dense_ln_phase(Wd, bd, gamma, beta, input, out, db, t, un, cta, tid);
        grid_barrier();
    }
}

extern "C" void kernel_launch(void* const* d_in, const int* in_sizes, int n_in,
                              void* d_out, int out_size) {
    (void)in_sizes; (void)n_in; (void)out_size;

    const int tot0 = (1280 / 8) * 4096, tot1 = (2048 / 8) * 4096;
    reorder_wb<<<(tot0 + 255) / 256, 256>>>((const float*)d_in[2], 0ull, 1280, 20);
    reorder_wb<<<(tot1 + 255) / 256, 256>>>((const float*)d_in[4], WB1_BASE, 2048, 32);
    reorder_wb<<<(tot1 + 255) / 256, 256>>>((const float*)d_in[6], WB2_BASE, 2048, 32);

    cudaFuncSetAttribute(lstm_mma, cudaFuncAttributeMaxDynamicSharedMemorySize, DSMEM);

    lstm_mma<<<NB, NT, DSMEM>>>(
        (const float*)d_in[0], (const unsigned char*)d_in[1],
        (const float*)d_in[3], (const float*)d_in[5], (const float*)d_in[7],
        (const float*)d_in[8], (const float*)d_in[9],
        (const float*)d_in[10], (const float*)d_in[11],
        (float*)d_out);
}

// round 14
// speedup vs baseline: 5.4410x; 1.0360x over previous
#include <cuda_runtime.h>
#include <cuda_bf16.h>
#include <cstdint>
#include <math.h>

#define T_STEPS 512
#define B_ROWS  64
#define F_DIM   256
#define U_DIM   1024
#define NB      128
#define NT      512
#define SW(x)   ((x) ^ (((x) >> 3) & 0x70))

#define WB1_BASE 10485760ull        // 128*20*4096 (ushorts)
#define WB2_BASE 27262976ull        // + 128*32*4096

#define STG_BYTES 24576             // Ah 8K | Al 8K | Bh 4K | Bl 4K
#define NSTG_G    4                 // stages per warp group
#define NSTG      8                 // total stage buffers
#define OFF_ZS    196608            // 8 stages end here
#define ZS_STRIDE 9216              // per-group partial z (64x36 floats)
#define DSMEM     215040            // 196608 + 2*9216

// ---------------- persistent device state ----------------
__device__ __align__(16) unsigned short g_WbT[44040192];     // [cta][chunk][hi2048|lo2048] swizzled
__device__ __align__(16) unsigned short g_x[2][4][4096];     // [hi/lo][chunk] 64x64 swizzled tiles
__device__ __align__(16) unsigned short g_hb[2][3][2][16][4096]; // [par][layer][hi/lo][chunk]
__device__ float g_c[3][B_ROWS][U_DIM];
__device__ float g_h2[B_ROWS * U_DIM];
__device__ unsigned g_bar_count = 0;
__device__ volatile unsigned g_bar_gen = 0;

// ---------------- weight reorder: fp32 [K][4096] -> swizzled per-CTA [n][k] hi/lo tiles ----------------
__global__ void reorder_wb(const float* __restrict__ W, unsigned long long base,
                           int K, int nch) {
    int idx = blockIdx.x * blockDim.x + threadIdx.x;
    int total = (K >> 3) * 4096;
    if (idx >= total) return;
    int n  = idx & 4095;
    int kb = (idx >> 12) << 3;
    int g = n >> 10, u = n & 1023;
    int cta = u >> 3, nloc = ((u & 7) << 2) | g;   // gate-interleaved column
    int chunk = kb >> 6, kc = kb & 63;
    unsigned hw[4], lw[4];
    #pragma unroll
    for (int i = 0; i < 4; i++) {
        float a = W[(size_t)(kb + 2 * i) * 4096 + n];
        float b = W[(size_t)(kb + 2 * i + 1) * 4096 + n];
        __nv_bfloat16 ha = __float2bfloat16(a), hb = __float2bfloat16(b);
        float ra = a - __bfloat162float(ha), rb = b - __bfloat162float(hb);
        hw[i] = (unsigned)__bfloat16_as_ushort(ha) | ((unsigned)__bfloat16_as_ushort(hb) << 16);
        lw[i] = (unsigned)__bfloat16_as_ushort(__float2bfloat16(ra))
              | ((unsigned)__bfloat16_as_ushort(__float2bfloat16(rb)) << 16);
    }
    size_t tb = base + (size_t)(cta * nch + chunk) * 4096;
    int off = SW(nloc * 128 + kc * 2) >> 1;
    *(uint4*)&g_WbT[tb + off]        = make_uint4(hw[0], hw[1], hw[2], hw[3]);
    *(uint4*)&g_WbT[tb + 2048 + off] = make_uint4(lw[0], lw[1], lw[2], lw[3]);
}

// ---------------- grid-wide barrier ----------------
__device__ __forceinline__ void grid_barrier() {
    __syncthreads();
    if (threadIdx.x == 0) {
        __threadfence();
        unsigned gen = g_bar_gen;
        if (atomicAdd(&g_bar_count, 1u) == (unsigned)(NB - 1)) {
            g_bar_count = 0;
            __threadfence();
            g_bar_gen = gen + 1u;
        } else {
            while (g_bar_gen == gen) { }
        }
    }
    __syncthreads();
    __threadfence();
}

// ---------------- ptx helpers ----------------
__device__ __forceinline__ float sigf(float x) { return 1.0f / (1.0f + expf(-x)); }

__device__ __forceinline__ void bulkcp(uint32_t dst, const void* src, uint32_t bytes,
                                       uint32_t mbar) {
    asm volatile(
        "cp.async.bulk.shared::cluster.global.mbarrier::complete_tx::bytes "
        "[%0], [%1], %2, [%3];"
        :: "r"(dst), "l"(src), "r"(bytes), "r"(mbar) : "memory");
}
__device__ __forceinline__ void mbar_init(uint32_t a, uint32_t c) {
    asm volatile("mbarrier.init.shared.b64 [%0], %1;" :: "r"(a), "r"(c) : "memory");
}
__device__ __forceinline__ void mbar_expect(uint32_t a, uint32_t bytes) {
    asm volatile("mbarrier.arrive.expect_tx.shared.b64 _, [%0], %1;"
                 :: "r"(a), "r"(bytes) : "memory");
}
__device__ __forceinline__ void mbar_wait(uint32_t a, int ph) {
    asm volatile(
        "{\n\t.reg .pred P;\n\t"
        "WL_%=:\n\t"
        "mbarrier.try_wait.parity.acquire.cta.shared::cta.b64 P, [%0], %1, 0x989680;\n\t"
        "@P bra.uni WD_%=;\n\tbra.uni WL_%=;\n\tWD_%=:\n\t}"
        :: "r"(a), "r"(ph) : "memory");
}
__device__ __forceinline__ void group_bar(int g) {
    asm volatile("bar.sync %0, 256;" :: "r"(g + 1) : "memory");
}
__device__ __forceinline__ void ldsm4(unsigned* r, uint32_t a) {
    asm volatile("ldmatrix.sync.aligned.m8n8.x4.shared.b16 {%0,%1,%2,%3}, [%4];"
                 : "=r"(r[0]), "=r"(r[1]), "=r"(r[2]), "=r"(r[3]) : "r"(a));
}
__device__ __forceinline__ void mma16816(float* d, const unsigned* a,
                                         unsigned b0, unsigned b1) {
    asm volatile(
        "mma.sync.aligned.m16n8k16.row.col.f32.bf16.bf16.f32 "
        "{%0,%1,%2,%3}, {%4,%5,%6,%7}, {%8,%9}, {%0,%1,%2,%3};"
        : "+f"(d[0]), "+f"(d[1]), "+f"(d[2]), "+f"(d[3])
        : "r"(a[0]), "r"(a[1]), "r"(a[2]), "r"(a[3]), "r"(b0), "r"(b1));
}

// ---------------- one LSTM layer: z = [feed, rec] @ W, fused gates ----------------
// 2 warp groups (8 warps each) split K by chunk parity; 4-deep bulk-copy pipeline each.
__device__ void layer_mma(
    const unsigned short* __restrict__ fh, const unsigned short* __restrict__ fl,
    int nf,
    const unsigned short* __restrict__ rh, const unsigned short* __restrict__ rl,
    const unsigned short* __restrict__ wb, int nch,
    const float* __restrict__ bias, float* __restrict__ Cst,
    unsigned short* __restrict__ whi, unsigned short* __restrict__ wlo,
    float* __restrict__ h2out,
    char* db, uint32_t s0, uint32_t mbb, int* ph, int cta, int tid)
{
    const int g   = tid >> 8;            // warp group 0/1
    const int gt  = tid & 255;
    const int lane = tid & 31, warp = gt >> 5;
    const int rg = warp & 3, cg = warp >> 2;
    const int l8 = lane & 7, gs = lane >> 3;
    const int arow = rg * 16 + l8 + (gs & 1) * 8;        // 0..63
    const int brow = cg * 16 + l8 + (gs & 1) * 8;        // 0..31
    const int cbase = (gs >> 1) * 16;
    const int nj = nch >> 1;             // chunks per group

    // separate accumulators per precision pass (shallow HMMA chains)
    float acc[3][2][4];
    #pragma unroll
    for (int p_ = 0; p_ < 3; p_++)
        #pragma unroll
        for (int c_ = 0; c_ < 2; c_++)
            #pragma unroll
            for (int f_ = 0; f_ < 4; f_++) acc[p_][c_][f_] = 0.f;

    auto issue = [&](int jj) {
        if (gt == 0) {
            int j = jj * 2 + g;
            int buf = g * NSTG_G + (jj & (NSTG_G - 1));
            uint32_t mb = mbb + buf * 8;
            mbar_expect(mb, STG_BYTES);
            const unsigned short *ah, *al;
            if (j < nf) { ah = fh + (size_t)j * 4096; al = fl + (size_t)j * 4096; }
            else { ah = rh + (size_t)(j - nf) * 4096; al = rl + (size_t)(j - nf) * 4096; }
            const unsigned short* wp = wb + (size_t)(cta * nch + j) * 4096;
            uint32_t d = s0 + buf * STG_BYTES;
            bulkcp(d,         ah, 8192, mb);
            bulkcp(d + 8192,  al, 8192, mb);
            bulkcp(d + 16384, wp, 4096, mb);
            bulkcp(d + 20480, wp + 2048, 4096, mb);
        }
    };

    #pragma unroll
    for (int j0 = 0; j0 < NSTG_G; j0++) if (j0 < nj) issue(j0);

    for (int jj = 0; jj < nj; jj++) {
        const int buf = g * NSTG_G + (jj & (NSTG_G - 1));
        mbar_wait(mbb + buf * 8, ph[buf]);
        ph[buf] ^= 1;

        const uint32_t bA  = s0 + buf * STG_BYTES;
        const uint32_t bAl = bA + 8192;
        const uint32_t bB  = bA + 16384;
        const uint32_t bBl = bA + 20480;

        #pragma unroll
        for (int s4 = 0; s4 < 4; s4++) {
            unsigned Ah[4], Al[4], Bh[4], Bl[4];
            const uint32_t ao = SW(arow * 128 + cbase + s4 * 32);
            const uint32_t bo = SW(brow * 128 + cbase + s4 * 32);
            ldsm4(Ah, bA  + ao);
            ldsm4(Bh, bB  + bo);
            ldsm4(Al, bAl + ao);
            ldsm4(Bl, bBl + bo);
            mma16816(acc[0][0], Ah, Bh[0], Bh[2]);
            mma16816(acc[0][1], Ah, Bh[1], Bh[3]);
            mma16816(acc[1][0], Ah, Bl[0], Bl[2]);
            mma16816(acc[1][1], Ah, Bl[1], Bl[3]);
            mma16816(acc[2][0], Al, Bh[0], Bh[2]);
            mma16816(acc[2][1], Al, Bh[1], Bh[3]);
        }
        group_bar(g);                  // group's warps done reading buf
        if (jj + NSTG_G < nj) issue(jj + NSTG_G);
    }

    // ---- dump group's partial z to its zs buffer ----
    float* zs = (float*)(db + OFF_ZS + g * ZS_STRIDE);
    {
        const int r_ = rg * 16 + (lane >> 2);
        const int cb = 2 * (lane & 3);
        #pragma unroll
        for (int s = 0; s < 2; s++) {
            int col = cg * 16 + s * 8 + cb;
            float v0 = acc[0][s][0] + acc[1][s][0] + acc[2][s][0];
            float v1 = acc[0][s][1] + acc[1][s][1] + acc[2][s][1];
            float v2 = acc[0][s][2] + acc[1][s][2] + acc[2][s][2];
            float v3 = acc[0][s][3] + acc[1][s][3] + acc[2][s][3];
            *(float2*)&zs[r_ * 36 + col]       = make_float2(v0, v1);
            *(float2*)&zs[(r_ + 8) * 36 + col] = make_float2(v2, v3);
        }
    }
    __syncthreads();

    // ---- fused gate update: 512 threads, 1 cell each ----
    {
        float* zs0 = (float*)(db + OFF_ZS);
        float* zs1 = (float*)(db + OFF_ZS + ZS_STRIDE);
        int row = tid >> 3, uu = tid & 7;
        float4 za = *(float4*)&zs0[row * 36 + uu * 4];
        float4 zb = *(float4*)&zs1[row * 36 + uu * 4];
        int u = cta * 8 + uu;
        float zi = za.x + zb.x + bias[u];
        float zj = za.y + zb.y + bias[1024 + u];
        float zf = za.z + zb.z + bias[2048 + u];
        float zo = za.w + zb.w + bias[3072 + u];
        float co = Cst[row * U_DIM + u];
        float cn = co * sigf(zf + 1.0f) + sigf(zi) * tanhf(zj);
        float hn = sigf(zo) * tanhf(cn);
        Cst[row * U_DIM + u] = cn;
        __nv_bfloat16 hh = __float2bfloat16(hn);
        float rr = hn - __bfloat162float(hh);
        int uc = u >> 6;
        int off = SW(row * 128 + (u & 63) * 2) >> 1;
        whi[uc * 4096 + off] = __bfloat16_as_ushort(hh);
        wlo[uc * 4096 + off] = __bfloat16_as_ushort(__float2bfloat16(rr));
        if (h2out) h2out[row * U_DIM + u] = hn;
    }
}

// ---------------- fused dense + layernorm + relu + emit (64 row-owner CTAs) ----------------
__device__ void dense_ln_phase(
    const float* __restrict__ Wd, const float* __restrict__ bd,
    const float* __restrict__ gamma, const float* __restrict__ beta,
    const float* __restrict__ input, float* __restrict__ out,
    char* db, int t, int use_next, int cta, int tid)
{
    if (cta >= B_ROWS) return;
    const int row = cta;
    float* h2s  = (float*)db;             // 4KB
    float* red2 = (float*)(db + 4096);    // 2KB
    float* red  = (float*)(db + 6144);    // 1KB

    ((float2*)h2s)[tid] = ((const float2*)(g_h2 + (size_t)row * U_DIM))[tid];
    __syncthreads();

    const int col = tid & 255;
    const int kh  = tid >> 8;
    const float* h2p = h2s + kh * 512;
    const float* wd  = Wd + (size_t)(kh * 512) * F_DIM + col;
    float acc = 0.0f;
    #pragma unroll 8
    for (int k = 0; k < 512; k++)
        acc = fmaf(h2p[k], wd[(size_t)k * F_DIM], acc);
    red2[tid] = acc;
    __syncthreads();

    float v = 0.0f;
    if (tid < 256) {
        v = red2[tid] + red2[tid + 256] + bd[tid];
        red[tid] = v;
    }
    __syncthreads();
    #pragma unroll
    for (int s = 128; s > 0; s >>= 1) {
        if (tid < s) red[tid] += red[tid + s];
        __syncthreads();
    }
    float mu = red[0] * (1.0f / 256.0f);
    __syncthreads();
    float dd = v - mu;
    if (tid < 256) red[tid] = dd * dd;
    __syncthreads();
    #pragma unroll
    for (int s = 128; s > 0; s >>= 1) {
        if (tid < s) red[tid] += red[tid + s];
        __syncthreads();
    }
    float var = red[0] * (1.0f / 256.0f);

    if (tid < 256) {
        float o = dd * rsqrtf(var + 1e-12f) * gamma[tid] + beta[tid];
        o = fmaxf(o, 0.0f);
        out[((size_t)row * T_STEPS + t) * F_DIM + tid] = o;
        if (t + 1 < T_STEPS) {
            float xn = use_next ? input[((size_t)row * T_STEPS + (t + 1)) * F_DIM + tid] : o;
            __nv_bfloat16 hh = __float2bfloat16(xn);
            float rr = xn - __bfloat162float(hh);
            int chunk = tid >> 6;
            int off = SW(row * 128 + (tid & 63) * 2) >> 1;
            g_x[0][chunk][off] = __bfloat16_as_ushort(hh);
            g_x[1][chunk][off] = __bfloat16_as_ushort(__float2bfloat16(rr));
        }
    }
}

// ---------------- persistent kernel ----------------
__global__ void __launch_bounds__(NT, 1) lstm_mma(
    const float* __restrict__ input, const unsigned char* __restrict__ condb,
    const float* __restrict__ b0, const float* __restrict__ b1,
    const float* __restrict__ b2,
    const float* __restrict__ Wd, const float* __restrict__ bd,
    const float* __restrict__ gamma, const float* __restrict__ beta,
    float* __restrict__ out)
{
    extern __shared__ __align__(128) char db[];
    const uint32_t s0 = (uint32_t)__cvta_generic_to_shared(db);

    __shared__ __align__(8) unsigned long long s_mb[NSTG];
    const uint32_t mbb = (uint32_t)__cvta_generic_to_shared(&s_mb[0]);

    const int cta = blockIdx.x, tid = threadIdx.x;
    int ph[NSTG] = {0, 0, 0, 0, 0, 0, 0, 0};

    if (tid == 0)
        for (int s = 0; s < NSTG; s++) mbar_init(mbb + s * 8, 1);
    __syncthreads();

    // detect dtype of conditioned_lst: bool-u8 vs int32 vs float32
    int p1 = 0, p23 = 0;
    for (int i = tid; i < T_STEPS; i += NT) {
        unsigned char bv = condb[i];
        if (bv != 0) { if ((i & 3) == 1) p1 = 1; if ((i & 3) >= 2) p23 = 1; }
    }
    const int is_u8  = __syncthreads_or(p1);
    const int is_f32 = __syncthreads_or(p23) && !is_u8;
    const int*   cond32 = (const int*)condb;
    const float* condf  = (const float*)condb;

    // zero c and h state; build x(0) tiles from input
    {
        float* cf = &g_c[0][0][0];
        for (int i = cta * NT + tid; i < 3 * B_ROWS * U_DIM; i += NB * NT) cf[i] = 0.0f;
        unsigned* hz = (unsigned*)&g_hb[0][0][0][0][0];
        for (int i = cta * NT + tid; i < 393216; i += NB * NT) hz[i] = 0u;
        for (int i = cta * NT + tid; i < B_ROWS * F_DIM; i += NB * NT) {
            int row = i >> 8, col = i & 255;
            float xv = input[(size_t)row * T_STEPS * F_DIM + col];
            __nv_bfloat16 hh = __float2bfloat16(xv);
            float rr = xv - __bfloat162float(hh);
            int chunk = col >> 6;
            int off = SW(row * 128 + (col & 63) * 2) >> 1;
            g_x[0][chunk][off] = __bfloat16_as_ushort(hh);
            g_x[1][chunk][off] = __bfloat16_as_ushort(__float2bfloat16(rr));
        }
    }
    grid_barrier();

    for (int t = 0; t < T_STEPS; t++) {
        const int p = t & 1, q = p ^ 1;
        int un = 0;
        if (t + 1 < T_STEPS) {
            if (is_u8)       un = (int)condb[t + 1];
            else if (is_f32) un = (condf[t + 1] != 0.0f);
            else             un = cond32[t + 1];
        }

        layer_mma(&g_x[0][0][0], &g_x[1][0][0], 4,
                  &g_hb[q][0][0][0][0], &g_hb[q][0][1][0][0],
                  g_WbT, 20, b0, &g_c[0][0][0],
                  &g_hb[p][0][0][0][0], &g_hb[p][0][1][0][0], nullptr,
                  db, s0, mbb, ph, cta, tid);
        grid_barrier();

        layer_mma(&g_hb[p][0][0][0][0], &g_hb[p][0][1][0][0], 16,
                  &g_hb[q][1][0][0][0], &g_hb[q][1][1][0][0],
                  g_WbT + WB1_BASE, 32, b1, &g_c[1][0][0],
                  &g_hb[p][1][0][0][0], &g_hb[p][1][1][0][0], nullptr,
                  db, s0, mbb, ph, cta, tid);
        grid_barrier();

        layer_mma(&g_hb[p][1][0][0][0], &g_hb[p][1][1][0][0], 16,
                  &g_hb[q][2][0][0][0], &g_hb[q][2][1][0][0],
                  g_WbT + WB2_BASE, 32, b2, &g_c[2][0][0],
                  &g_hb[p][2][0][0][0], &g_hb[p][2][1][0][0], g_h2,
                  db, s0, mbb, ph, cta, tid);
        grid_barrier();

        dense_ln_phase(Wd, bd, gamma, beta, input, out, db, t, un, cta, tid);
        grid_barrier();
    }
}

extern "C" void kernel_launch(void* const* d_in, const int* in_sizes, int n_in,
                              void* d_out, int out_size) {
    (void)in_sizes; (void)n_in; (void)out_size;

    const int tot0 = (1280 / 8) * 4096, tot1 = (2048 / 8) * 4096;
    reorder_wb<<<(tot0 + 255) / 256, 256>>>((const float*)d_in[2], 0ull, 1280, 20);
    reorder_wb<<<(tot1 + 255) / 256, 256>>>((const float*)d_in[4], WB1_BASE, 2048, 32);
    reorder_wb<<<(tot1 + 255) / 256, 256>>>((const float*)d_in[6], WB2_BASE, 2048, 32);

    cudaFuncSetAttribute(lstm_mma, cudaFuncAttributeMaxDynamicSharedMemorySize, DSMEM);

    lstm_mma<<<NB, NT, DSMEM>>>(
        (const float*)d_in[0], (const unsigned char*)d_in[1],
        (const float*)d_in[3], (const float*)d_in[5], (const float*)d_in[7],
        (const float*)d_in[8], (const float*)d_in[9],
        (const float*)d_in[10], (const float*)d_in[11],
        (float*)d_out);
}

// round 17
// speedup vs baseline: 6.0619x; 1.1141x over previous
#include <cuda_runtime.h>
#include <cuda_bf16.h>
#include <cstdint>
#include <math.h>

#define T_STEPS 512
#define B_ROWS  64
#define F_DIM   256
#define U_DIM   1024
#define NB      128
#define NT      512
#define SW(x)   ((x) ^ (((x) >> 3) & 0x70))

#define WB1_BASE 10485760ull        // 128*20*4096 (ushorts)
#define WB2_BASE 27262976ull        // + 128*32*4096

#define STG_BYTES 24576             // Ah 8K | Al 8K | Bh 4K | Bl 4K
#define NSTG_G    2                 // stages per warp group
#define NSTG      8                 // total stage buffers (4 groups x 2)
#define ZS_STRIDE 36                // floats per row in partial z
#define DSMEM     196608            // 8 stages; zs aliases group buffer 0

// ---------------- persistent device state ----------------
__device__ __align__(16) unsigned short g_WbT[44040192];     // [cta][chunk][hi2048|lo2048] swizzled
__device__ __align__(16) unsigned short g_x[2][4][4096];     // [hi/lo][chunk] 64x64 swizzled tiles
__device__ __align__(16) unsigned short g_hb[2][3][2][16][4096]; // [par][layer][hi/lo][chunk]
__device__ float g_c[3][B_ROWS][U_DIM];
__device__ float g_h2[B_ROWS * U_DIM];
__device__ unsigned g_bar_count = 0;
__device__ volatile unsigned g_bar_gen = 0;

// ---------------- weight reorder: fp32 [K][4096] -> swizzled per-CTA [n][k] hi/lo tiles ----------------
__global__ void reorder_wb(const float* __restrict__ W, unsigned long long base,
                           int K, int nch) {
    int idx = blockIdx.x * blockDim.x + threadIdx.x;
    int total = (K >> 3) * 4096;
    if (idx >= total) return;
    int n  = idx & 4095;
    int kb = (idx >> 12) << 3;
    int g = n >> 10, u = n & 1023;
    int cta = u >> 3, nloc = ((u & 7) << 2) | g;   // gate-interleaved column
    int chunk = kb >> 6, kc = kb & 63;
    unsigned hw[4], lw[4];
    #pragma unroll
    for (int i = 0; i < 4; i++) {
        float a = W[(size_t)(kb + 2 * i) * 4096 + n];
        float b = W[(size_t)(kb + 2 * i + 1) * 4096 + n];
        __nv_bfloat16 ha = __float2bfloat16(a), hb = __float2bfloat16(b);
        float ra = a - __bfloat162float(ha), rb = b - __bfloat162float(hb);
        hw[i] = (unsigned)__bfloat16_as_ushort(ha) | ((unsigned)__bfloat16_as_ushort(hb) << 16);
        lw[i] = (unsigned)__bfloat16_as_ushort(__float2bfloat16(ra))
              | ((unsigned)__bfloat16_as_ushort(__float2bfloat16(rb)) << 16);
    }
    size_t tb = base + (size_t)(cta * nch + chunk) * 4096;
    int off = SW(nloc * 128 + kc * 2) >> 1;
    *(uint4*)&g_WbT[tb + off]        = make_uint4(hw[0], hw[1], hw[2], hw[3]);
    *(uint4*)&g_WbT[tb + 2048 + off] = make_uint4(lw[0], lw[1], lw[2], lw[3]);
}

// ---------------- grid-wide barrier ----------------
__device__ __forceinline__ void grid_barrier() {
    __syncthreads();
    if (threadIdx.x == 0) {
        __threadfence();
        unsigned gen = g_bar_gen;
        if (atomicAdd(&g_bar_count, 1u) == (unsigned)(NB - 1)) {
            g_bar_count = 0;
            __threadfence();
            g_bar_gen = gen + 1u;
        } else {
            while (g_bar_gen == gen) { }
        }
    }
    __syncthreads();
    __threadfence();
}

// ---------------- ptx helpers ----------------
__device__ __forceinline__ float sigf(float x) { return 1.0f / (1.0f + expf(-x)); }

__device__ __forceinline__ void bulkcp(uint32_t dst, const void* src, uint32_t bytes,
                                       uint32_t mbar) {
    asm volatile(
        "cp.async.bulk.shared::cluster.global.mbarrier::complete_tx::bytes "
        "[%0], [%1], %2, [%3];"
        :: "r"(dst), "l"(src), "r"(bytes), "r"(mbar) : "memory");
}
__device__ __forceinline__ void mbar_init(uint32_t a, uint32_t c) {
    asm volatile("mbarrier.init.shared.b64 [%0], %1;" :: "r"(a), "r"(c) : "memory");
}
__device__ __forceinline__ void mbar_expect(uint32_t a, uint32_t bytes) {
    asm volatile("mbarrier.arrive.expect_tx.shared.b64 _, [%0], %1;"
                 :: "r"(a), "r"(bytes) : "memory");
}
__device__ __forceinline__ void mbar_wait(uint32_t a, int ph) {
    asm volatile(
        "{\n\t.reg .pred P;\n\t"
        "WL_%=:\n\t"
        "mbarrier.try_wait.parity.acquire.cta.shared::cta.b64 P, [%0], %1, 0x989680;\n\t"
        "@P bra.uni WD_%=;\n\tbra.uni WL_%=;\n\tWD_%=:\n\t}"
        :: "r"(a), "r"(ph) : "memory");
}
__device__ __forceinline__ void group_bar(int g) {
    asm volatile("bar.sync %0, 128;" :: "r"(g + 1) : "memory");
}
__device__ __forceinline__ void ldsm4(unsigned* r, uint32_t a) {
    asm volatile("ldmatrix.sync.aligned.m8n8.x4.shared.b16 {%0,%1,%2,%3}, [%4];"
                 : "=r"(r[0]), "=r"(r[1]), "=r"(r[2]), "=r"(r[3]) : "r"(a));
}
__device__ __forceinline__ void mma16816(float* d, const unsigned* a,
                                         unsigned b0, unsigned b1) {
    asm volatile(
        "mma.sync.aligned.m16n8k16.row.col.f32.bf16.bf16.f32 "
        "{%0,%1,%2,%3}, {%4,%5,%6,%7}, {%8,%9}, {%0,%1,%2,%3};"
        : "+f"(d[0]), "+f"(d[1]), "+f"(d[2]), "+f"(d[3])
        : "r"(a[0]), "r"(a[1]), "r"(a[2]), "r"(a[3]), "r"(b0), "r"(b1));
}

// ---------------- one LSTM layer: z = [feed, rec] @ W, fused gates ----------------
// 4 warp groups (4 warps each) split K by chunk mod 4; warp tile 16x32.
__device__ void layer_mma(
    const unsigned short* __restrict__ fh, const unsigned short* __restrict__ fl,
    int nf,
    const unsigned short* __restrict__ rh, const unsigned short* __restrict__ rl,
    const unsigned short* __restrict__ wb, int nch,
    const float* __restrict__ bias, float* __restrict__ Cst,
    unsigned short* __restrict__ whi, unsigned short* __restrict__ wlo,
    float* __restrict__ h2out,
    char* db, uint32_t s0, uint32_t mbb, int* ph, int cta, int tid)
{
    const int g    = tid >> 7;           // warp group 0..3
    const int gt   = tid & 127;
    const int lane = tid & 31, warp = gt >> 5;   // warp 0..3 in group
    const int l8 = lane & 7, gs = lane >> 3;
    const int arow  = warp * 16 + l8 + (gs & 1) * 8;   // 0..63
    const int brow0 = l8 + (gs & 1) * 8;               // n 0..15
    const int cbase = (gs >> 1) * 16;
    const int nj = nch >> 2;             // chunks per group

    // acc[pass][n8][frag] - shallow HMMA chains
    float acc[3][4][4];
    #pragma unroll
    for (int p_ = 0; p_ < 3; p_++)
        #pragma unroll
        for (int c_ = 0; c_ < 4; c_++)
            #pragma unroll
            for (int f_ = 0; f_ < 4; f_++) acc[p_][c_][f_] = 0.f;

    auto issue = [&](int jj) {
        if (gt == 0) {
            int j = jj * 4 + g;
            int buf = g * NSTG_G + (jj & (NSTG_G - 1));
            uint32_t mb = mbb + buf * 8;
            mbar_expect(mb, STG_BYTES);
            const unsigned short *ah, *al;
            if (j < nf) { ah = fh + (size_t)j * 4096; al = fl + (size_t)j * 4096; }
            else { ah = rh + (size_t)(j - nf) * 4096; al = rl + (size_t)(j - nf) * 4096; }
            const unsigned short* wp = wb + (size_t)(cta * nch + j) * 4096;
            uint32_t d = s0 + buf * STG_BYTES;
            bulkcp(d,         ah, 8192, mb);
            bulkcp(d + 8192,  al, 8192, mb);
            bulkcp(d + 16384, wp, 4096, mb);
            bulkcp(d + 20480, wp + 2048, 4096, mb);
        }
    };

    issue(0);
    if (nj > 1) issue(1);

    for (int jj = 0; jj < nj; jj++) {
        const int buf = g * NSTG_G + (jj & (NSTG_G - 1));
        mbar_wait(mbb + buf * 8, ph[buf]);
        ph[buf] ^= 1;

        const uint32_t bA  = s0 + buf * STG_BYTES;
        const uint32_t bAl = bA + 8192;
        const uint32_t bB  = bA + 16384;
        const uint32_t bBl = bA + 20480;

        #pragma unroll
        for (int s4 = 0; s4 < 4; s4++) {
            unsigned Ah[4], Al[4], Bh0[4], Bh1[4], Bl0[4], Bl1[4];
            const uint32_t ao  = SW(arow * 128 + cbase + s4 * 32);
            const uint32_t bo0 = SW(brow0 * 128 + cbase + s4 * 32);
            const uint32_t bo1 = SW((brow0 + 16) * 128 + cbase + s4 * 32);
            ldsm4(Ah,  bA  + ao);
            ldsm4(Bh0, bB  + bo0);
            ldsm4(Bh1, bB  + bo1);
            ldsm4(Al,  bAl + ao);
            ldsm4(Bl0, bBl + bo0);
            ldsm4(Bl1, bBl + bo1);
            // pass 0: Ah * Bh
            mma16816(acc[0][0], Ah, Bh0[0], Bh0[2]);
            mma16816(acc[0][1], Ah, Bh0[1], Bh0[3]);
            mma16816(acc[0][2], Ah, Bh1[0], Bh1[2]);
            mma16816(acc[0][3], Ah, Bh1[1], Bh1[3]);
            // pass 1: Ah * Bl
            mma16816(acc[1][0], Ah, Bl0[0], Bl0[2]);
            mma16816(acc[1][1], Ah, Bl0[1], Bl0[3]);
            mma16816(acc[1][2], Ah, Bl1[0], Bl1[2]);
            mma16816(acc[1][3], Ah, Bl1[1], Bl1[3]);
            // pass 2: Al * Bh
            mma16816(acc[2][0], Al, Bh0[0], Bh0[2]);
            mma16816(acc[2][1], Al, Bh0[1], Bh0[3]);
            mma16816(acc[2][2], Al, Bh1[0], Bh1[2]);
            mma16816(acc[2][3], Al, Bh1[1], Bh1[3]);
        }
        group_bar(g);                  // group's warps done reading buf
        if (jj + NSTG_G < nj) issue(jj + NSTG_G);
    }

    // ---- dump group's partial z into its (now idle) stage-buffer-0 region ----
    float* zs = (float*)(db + g * (NSTG_G * STG_BYTES));
    {
        const int r_ = warp * 16 + (lane >> 2);
        const int cb = 2 * (lane & 3);
        #pragma unroll
        for (int s = 0; s < 4; s++) {
            int col = s * 8 + cb;
            float v0 = acc[0][s][0] + acc[1][s][0] + acc[2][s][0];
            float v1 = acc[0][s][1] + acc[1][s][1] + acc[2][s][1];
            float v2 = acc[0][s][2] + acc[1][s][2] + acc[2][s][2];
            float v3 = acc[0][s][3] + acc[1][s][3] + acc[2][s][3];
            *(float2*)&zs[r_ * ZS_STRIDE + col]       = make_float2(v0, v1);
            *(float2*)&zs[(r_ + 8) * ZS_STRIDE + col] = make_float2(v2, v3);
        }
    }
    __syncthreads();

    // ---- fused gate update: 512 threads, 1 cell each; sum 4 group partials ----
    {
        int row = tid >> 3, uu = tid & 7;
        float4 z0 = *(float4*)((float*)(db + 0 * NSTG_G * STG_BYTES) + row * ZS_STRIDE + uu * 4);
        float4 z1 = *(float4*)((float*)(db + 1 * NSTG_G * STG_BYTES) + row * ZS_STRIDE + uu * 4);
        float4 z2 = *(float4*)((float*)(db + 2 * NSTG_G * STG_BYTES) + row * ZS_STRIDE + uu * 4);
        float4 z3 = *(float4*)((float*)(db + 3 * NSTG_G * STG_BYTES) + row * ZS_STRIDE + uu * 4);
        int u = cta * 8 + uu;
        float zi = z0.x + z1.x + z2.x + z3.x + bias[u];
        float zj = z0.y + z1.y + z2.y + z3.y + bias[1024 + u];
        float zf = z0.z + z1.z + z2.z + z3.z + bias[2048 + u];
        float zo = z0.w + z1.w + z2.w + z3.w + bias[3072 + u];
        float co = Cst[row * U_DIM + u];
        float cn = co * sigf(zf + 1.0f) + sigf(zi) * tanhf(zj);
        float hn = sigf(zo) * tanhf(cn);
        Cst[row * U_DIM + u] = cn;
        __nv_bfloat16 hh = __float2bfloat16(hn);
        float rr = hn - __bfloat162float(hh);
        int uc = u >> 6;
        int off = SW(row * 128 + (u & 63) * 2) >> 1;
        whi[uc * 4096 + off] = __bfloat16_as_ushort(hh);
        wlo[uc * 4096 + off] = __bfloat16_as_ushort(__float2bfloat16(rr));
        if (h2out) h2out[row * U_DIM + u] = hn;
    }
}

// ---------------- fused dense + layernorm + relu + emit (64 row-owner CTAs) ----------------
__device__ void dense_ln_phase(
    const float* __restrict__ Wd, const float* __restrict__ bd,
    const float* __restrict__ gamma, const float* __restrict__ beta,
    const float* __restrict__ input, float* __restrict__ out,
    char* db, int t, int use_next, int cta, int tid)
{
    if (cta >= B_ROWS) return;
    const int row = cta;
    float* h2s  = (float*)db;             // 4KB
    float* red2 = (float*)(db + 4096);    // 2KB
    float* red  = (float*)(db + 6144);    // 1KB

    ((float2*)h2s)[tid] = ((const float2*)(g_h2 + (size_t)row * U_DIM))[tid];
    __syncthreads();

    const int col = tid & 255;
    const int kh  = tid >> 8;
    const float* h2p = h2s + kh * 512;
    const float* wd  = Wd + (size_t)(kh * 512) * F_DIM + col;
    float acc = 0.0f;
    #pragma unroll 8
    for (int k = 0; k < 512; k++)
        acc = fmaf(h2p[k], wd[(size_t)k * F_DIM], acc);
    red2[tid] = acc;
    __syncthreads();

    float v = 0.0f;
    if (tid < 256) {
        v = red2[tid] + red2[tid + 256] + bd[tid];
        red[tid] = v;
    }
    __syncthreads();
    #pragma unroll
    for (int s = 128; s > 0; s >>= 1) {
        if (tid < s) red[tid] += red[tid + s];
        __syncthreads();
    }
    float mu = red[0] * (1.0f / 256.0f);
    __syncthreads();
    float dd = v - mu;
    if (tid < 256) red[tid] = dd * dd;
    __syncthreads();
    #pragma unroll
    for (int s = 128; s > 0; s >>= 1) {
        if (tid < s) red[tid] += red[tid + s];
        __syncthreads();
    }
    float var = red[0] * (1.0f / 256.0f);

    if (tid < 256) {
        float o = dd * rsqrtf(var + 1e-12f) * gamma[tid] + beta[tid];
        o = fmaxf(o, 0.0f);
        out[((size_t)row * T_STEPS + t) * F_DIM + tid] = o;
        if (t + 1 < T_STEPS) {
            float xn = use_next ? input[((size_t)row * T_STEPS + (t + 1)) * F_DIM + tid] : o;
            __nv_bfloat16 hh = __float2bfloat16(xn);
            float rr = xn - __bfloat162float(hh);
            int chunk = tid >> 6;
            int off = SW(row * 128 + (tid & 63) * 2) >> 1;
            g_x[0][chunk][off] = __bfloat16_as_ushort(hh);
            g_x[1][chunk][off] = __bfloat16_as_ushort(__float2bfloat16(rr));
        }
    }
}

// ---------------- persistent kernel ----------------
__global__ void __launch_bounds__(NT, 1) lstm_mma(
    const float* __restrict__ input, const unsigned char* __restrict__ condb,
    const float* __restrict__ b0, const float* __restrict__ b1,
    const float* __restrict__ b2,
    const float* __restrict__ Wd, const float* __restrict__ bd,
    const float* __restrict__ gamma, const float* __restrict__ beta,
    float* __restrict__ out)
{
    extern __shared__ __align__(128) char db[];
    const uint32_t s0 = (uint32_t)__cvta_generic_to_shared(db);

    __shared__ __align__(8) unsigned long long s_mb[NSTG];
    const uint32_t mbb = (uint32_t)__cvta_generic_to_shared(&s_mb[0]);

    const int cta = blockIdx.x, tid = threadIdx.x;
    int ph[NSTG] = {0, 0, 0, 0, 0, 0, 0, 0};

    if (tid == 0)
        for (int s = 0; s < NSTG; s++) mbar_init(mbb + s * 8, 1);
    __syncthreads();

    // detect dtype of conditioned_lst: bool-u8 vs int32 vs float32
    int p1 = 0, p23 = 0;
    for (int i = tid; i < T_STEPS; i += NT) {
        unsigned char bv = condb[i];
        if (bv != 0) { if ((i & 3) == 1) p1 = 1; if ((i & 3) >= 2) p23 = 1; }
    }
    const int is_u8  = __syncthreads_or(p1);
    const int is_f32 = __syncthreads_or(p23) && !is_u8;
    const int*   cond32 = (const int*)condb;
    const float* condf  = (const float*)condb;

    // zero c and h state; build x(0) tiles from input
    {
        float* cf = &g_c[0][0][0];
        for (int i = cta * NT + tid; i < 3 * B_ROWS * U_DIM; i += NB * NT) cf[i] = 0.0f;
        unsigned* hz = (unsigned*)&g_hb[0][0][0][0][0];
        for (int i = cta * NT + tid; i < 393216; i += NB * NT) hz[i] = 0u;
        for (int i = cta * NT + tid; i < B_ROWS * F_DIM; i += NB * NT) {
            int row = i >> 8, col = i & 255;
            float xv = input[(size_t)row * T_STEPS * F_DIM + col];
            __nv_bfloat16 hh = __float2bfloat16(xv);
            float rr = xv - __bfloat162float(hh);
            int chunk = col >> 6;
            int off = SW(row * 128 + (col & 63) * 2) >> 1;
            g_x[0][chunk][off] = __bfloat16_as_ushort(hh);
            g_x[1][chunk][off] = __bfloat16_as_ushort(__float2bfloat16(rr));
        }
    }
    grid_barrier();

    for (int t = 0; t < T_STEPS; t++) {
        const int p = t & 1, q = p ^ 1;
        int un = 0;
        if (t + 1 < T_STEPS) {
            if (is_u8)       un = (int)condb[t + 1];
            else if (is_f32) un = (condf[t + 1] != 0.0f);
            else             un = cond32[t + 1];
        }

        layer_mma(&g_x[0][0][0], &g_x[1][0][0], 4,
                  &g_hb[q][0][0][0][0], &g_hb[q][0][1][0][0],
                  g_WbT, 20, b0, &g_c[0][0][0],
                  &g_hb[p][0][0][0][0], &g_hb[p][0][1][0][0], nullptr,
                  db, s0, mbb, ph, cta, tid);
        grid_barrier();

        layer_mma(&g_hb[p][0][0][0][0], &g_hb[p][0][1][0][0], 16,
                  &g_hb[q][1][0][0][0], &g_hb[q][1][1][0][0],
                  g_WbT + WB1_BASE, 32, b1, &g_c[1][0][0],
                  &g_hb[p][1][0][0][0], &g_hb[p][1][1][0][0], nullptr,
                  db, s0, mbb, ph, cta, tid);
        grid_barrier();

        layer_mma(&g_hb[p][1][0][0][0], &g_hb[p][1][1][0][0], 16,
                  &g_hb[q][2][0][0][0], &g_hb[q][2][1][0][0],
                  g_WbT + WB2_BASE, 32, b2, &g_c[2][0][0],
                  &g_hb[p][2][0][0][0], &g_hb[p][2][1][0][0], g_h2,
                  db, s0, mbb, ph, cta, tid);
        grid_barrier();

        dense_ln_phase(Wd, bd, gamma, beta, input, out, db, t, un, cta, tid);
        grid_barrier();
    }
}

extern "C" void kernel_launch(void* const* d_in, const int* in_sizes, int n_in,
                              void* d_out, int out_size) {
    (void)in_sizes; (void)n_in; (void)out_size;

    const int tot0 = (1280 / 8) * 4096, tot1 = (2048 / 8) * 4096;
    reorder_wb<<<(tot0 + 255) / 256, 256>>>((const float*)d_in[2], 0ull, 1280, 20);
    reorder_wb<<<(tot1 + 255) / 256, 256>>>((const float*)d_in[4], WB1_BASE, 2048, 32);
    reorder_wb<<<(tot1 + 255) / 256, 256>>>((const float*)d_in[6], WB2_BASE, 2048, 32);

    cudaFuncSetAttribute(lstm_mma, cudaFuncAttributeMaxDynamicSharedMemorySize, DSMEM);

    lstm_mma<<<NB, NT, DSMEM>>>(
        (const float*)d_in[0], (const unsigned char*)d_in[1],
        (const float*)d_in[3], (const float*)d_in[5], (const float*)d_in[7],
        (const float*)d_in[8], (const float*)d_in[9],
        (const float*)d_in[10], (const float*)d_in[11],
        (float*)d_out);
}